// round 2
// baseline (speedup 1.0000x reference)
#include <cuda_runtime.h>
#include <cstdint>

#define BB 64
#define SS 400
#define HH 512
#define EE 300
#define VOCAB 50000
#define KOUT 1024   // 2H
#define KG   1324   // E + H + H
#define GR   2048   // 4H

#define OUT_H_OFF (BB * VOCAB)
#define OUT_C_OFF (BB * VOCAB + BB * HH)

// ---------------- scratch (device globals; no allocations allowed) ----------
__device__ float g_attw[BB * SS];
__device__ float g_xeT[EE * BB];     // [e][b]
__device__ float g_ctxT[HH * BB];    // [h][b]
__device__ float g_hprevT[HH * BB];  // [h][b]
__device__ float g_hnewT[HH * BB];   // [h][b]
__device__ float g_gates[BB * GR];   // [b][r]
__device__ float g_pgen[BB];

// ---------------- helpers ----------------------------------------------------
typedef unsigned long long ull;

__device__ __forceinline__ ull pack2(float lo, float hi) {
    ull r; asm("mov.b64 %0,{%1,%2};" : "=l"(r) : "f"(lo), "f"(hi)); return r;
}
__device__ __forceinline__ void unpack2(ull v, float& lo, float& hi) {
    asm("mov.b64 {%0,%1},%2;" : "=f"(lo), "=f"(hi) : "l"(v));
}
__device__ __forceinline__ void fma2(ull& d, ull a, ull b) {
    asm("fma.rn.f32x2 %0,%1,%2,%3;" : "=l"(d) : "l"(a), "l"(b), "l"(d));
}

__device__ __forceinline__ float fast_tanh(float x) {
    // tanh(x) = 1 - 2/(exp(2x)+1); exp overflow/underflow -> exact +-1
    float e = __expf(x + x);
    return 1.f - __fdividef(2.f, e + 1.f);
}
__device__ __forceinline__ float fast_sigm(float x) {
    return __fdividef(1.f, 1.f + __expf(-x));
}

// ---------------- embedding gather (transposed) ------------------------------
__global__ void k_embed(const int* __restrict__ x, const float* __restrict__ emb) {
    int t = threadIdx.x;
    int b = t & 63;
    int e = blockIdx.x * 4 + (t >> 6);
    if (e < EE) g_xeT[e * BB + b] = emb[(size_t)x[b] * EE + e];
}

// ---------------- attention: scores -> softmax -> ctx ------------------------
__global__ void k_attn(const float* __restrict__ enc, const float* __restrict__ h0,
                       const float* __restrict__ Vw, const float* __restrict__ Vb) {
    __shared__ float sh_h[HH];
    __shared__ float sh_vw[HH];
    __shared__ float sh_sc[SS];
    __shared__ float sh_red[8];

    int b = blockIdx.x;
    int t = threadIdx.x;
    int lane = t & 31, w = t >> 5;

    for (int i = t; i < HH; i += 256) {
        float hv = h0[b * HH + i];
        sh_h[i] = hv;
        g_hprevT[i * BB + b] = hv;
        sh_vw[i] = Vw[i];
    }
    __syncthreads();

    const float* encb = enc + (size_t)b * (SS * HH);
    float vb = Vb[0];

    // phase A: scores (warp per s)
    for (int s = w; s < SS; s += 8) {
        const float* row = encb + s * HH;
        float p = 0.f;
#pragma unroll
        for (int j = 0; j < 16; j++) {
            int h = j * 32 + lane;
            p += fast_tanh(row[h] + sh_h[h]) * sh_vw[h];
        }
#pragma unroll
        for (int o = 16; o; o >>= 1) p += __shfl_xor_sync(~0u, p, o);
        if (lane == 0) sh_sc[s] = p + vb;
    }
    __syncthreads();

    // phase B: softmax over S
    float m = -3.4e38f;
    for (int s = t; s < SS; s += 256) m = fmaxf(m, sh_sc[s]);
#pragma unroll
    for (int o = 16; o; o >>= 1) m = fmaxf(m, __shfl_xor_sync(~0u, m, o));
    if (lane == 0) sh_red[w] = m;
    __syncthreads();
    m = sh_red[0];
#pragma unroll
    for (int i = 1; i < 8; i++) m = fmaxf(m, sh_red[i]);
    __syncthreads();

    float ssum = 0.f;
    for (int s = t; s < SS; s += 256) {
        float e = __expf(sh_sc[s] - m);
        sh_sc[s] = e;
        ssum += e;
    }
#pragma unroll
    for (int o = 16; o; o >>= 1) ssum += __shfl_xor_sync(~0u, ssum, o);
    if (lane == 0) sh_red[w] = ssum;
    __syncthreads();
    ssum = 0.f;
#pragma unroll
    for (int i = 0; i < 8; i++) ssum += sh_red[i];
    float inv = 1.f / ssum;

    for (int s = t; s < SS; s += 256) {
        float wv = sh_sc[s] * inv;
        sh_sc[s] = wv;
        g_attw[b * SS + s] = wv;
    }
    __syncthreads();

    // phase C: ctx[h] = sum_s w[s] * enc[b,s,h]; thread handles h=t, t+256
    float a0 = 0.f, a1 = 0.f;
#pragma unroll 4
    for (int s = 0; s < SS; s++) {
        float wv = sh_sc[s];
        a0 = fmaf(wv, encb[s * HH + t], a0);
        a1 = fmaf(wv, encb[s * HH + t + 256], a1);
    }
    g_ctxT[t * BB + b] = a0;
    g_ctxT[(t + 256) * BB + b] = a1;
}

// ---------------- gate bias init ---------------------------------------------
__global__ void k_gbias(const float* __restrict__ bih, const float* __restrict__ bhh) {
    int idx = blockIdx.x * 256 + threadIdx.x;
    if (idx < BB * GR) {
        int r = idx & (GR - 1);
        g_gates[idx] = bih[r] + bhh[r];
    }
}

// ---------------- gates GEMM: [64 x 2048] = d_in_ext[64,1324] @ Wcat^T -------
// BM=64, BN=128, BK=16, split-K x8, 256 threads, per-thread 4(m) x 8(n)
__global__ void __launch_bounds__(256) k_gates(const float* __restrict__ Wih,
                                               const float* __restrict__ Whh) {
    __shared__ float As[16][64];
    __shared__ float Bs[16][128];
    int t = threadIdx.x;
    int r0 = blockIdx.x * 128;     // grid.x = 16
    int kbase = blockIdx.y * 176;  // grid.y = 8 -> covers 1408 >= 1324
    int j = t & 15, i = t >> 4;
    int m0 = i * 4, n0 = j * 8;

    ull acc[4][4];
#pragma unroll
    for (int a = 0; a < 4; a++)
#pragma unroll
        for (int p = 0; p < 4; p++) acc[a][p] = pack2(0.f, 0.f);

    int rl = t & 127, kh = t >> 7;
    int r = r0 + rl;

    for (int k0 = kbase; k0 < kbase + 176; k0 += 16) {
        // A tile: [kk][m] from transposed scratch (xe | ctx | hprev)
#pragma unroll
        for (int q = 0; q < 4; q++) {
            int idx = t * 4 + q;
            int kk = idx >> 6, mm = idx & 63;
            int k = k0 + kk;
            float v;
            if (k >= KG) v = 0.f;
            else if (k < EE) v = g_xeT[k * BB + mm];
            else if (k < EE + HH) v = g_ctxT[(k - EE) * BB + mm];
            else v = g_hprevT[(k - EE - HH) * BB + mm];
            As[kk][mm] = v;
        }
        // B tile: row r, 8 k's per thread (piecewise Wih|Whh)
#pragma unroll
        for (int g = 0; g < 2; g++) {
            int k = k0 + kh * 8 + g * 4;
            float4 v;
            if (k + 3 < 812) {
                v = *reinterpret_cast<const float4*>(Wih + (size_t)r * 812 + k);
            } else if (k >= 812 && k + 3 < KG) {
                v = *reinterpret_cast<const float4*>(Whh + (size_t)r * 512 + (k - 812));
            } else {
                float tmp[4];
#pragma unroll
                for (int q = 0; q < 4; q++) {
                    int kq = k + q;
                    tmp[q] = (kq < 812) ? Wih[(size_t)r * 812 + kq]
                           : (kq < KG) ? Whh[(size_t)r * 512 + (kq - 812)] : 0.f;
                }
                v = make_float4(tmp[0], tmp[1], tmp[2], tmp[3]);
            }
            int kk = kh * 8 + g * 4;
            Bs[kk + 0][rl] = v.x; Bs[kk + 1][rl] = v.y;
            Bs[kk + 2][rl] = v.z; Bs[kk + 3][rl] = v.w;
        }
        __syncthreads();
#pragma unroll
        for (int kk = 0; kk < 16; kk++) {
            float4 a4 = *reinterpret_cast<const float4*>(&As[kk][m0]);
            ull ad[4] = {pack2(a4.x, a4.x), pack2(a4.y, a4.y),
                         pack2(a4.z, a4.z), pack2(a4.w, a4.w)};
            const ull* br = reinterpret_cast<const ull*>(&Bs[kk][n0]);
            ull bv[4] = {br[0], br[1], br[2], br[3]};
#pragma unroll
            for (int mm = 0; mm < 4; mm++)
#pragma unroll
                for (int p = 0; p < 4; p++) fma2(acc[mm][p], ad[mm], bv[p]);
        }
        __syncthreads();
    }
#pragma unroll
    for (int mm = 0; mm < 4; mm++) {
        int b_ = m0 + mm;
#pragma unroll
        for (int p = 0; p < 4; p++) {
            float lo, hi;
            unpack2(acc[mm][p], lo, hi);
            int rr = r0 + n0 + 2 * p;
            atomicAdd(&g_gates[b_ * GR + rr], lo);
            atomicAdd(&g_gates[b_ * GR + rr + 1], hi);
        }
    }
}

// ---------------- LSTM elementwise -------------------------------------------
__global__ void k_lstm(const float* __restrict__ c0, float* __restrict__ out) {
    int idx = blockIdx.x * 256 + threadIdx.x;  // 0..32767
    int b = idx >> 9, h = idx & (HH - 1);
    const float* g = g_gates + b * GR;
    float gi = g[h], gf = g[HH + h], gg = g[2 * HH + h], go = g[3 * HH + h];
    float c = fast_sigm(gf) * c0[idx] + fast_sigm(gi) * fast_tanh(gg);
    float hn = fast_sigm(go) * fast_tanh(c);
    out[OUT_H_OFF + idx] = hn;
    out[OUT_C_OFF + idx] = c;
    g_hnewT[h * BB + b] = hn;
}

// ---------------- p_gen: sigmoid(gen_w . [ctx, h_new, xe] + gen_b) -----------
__global__ void k_pgen(const float* __restrict__ genw, const float* __restrict__ genb) {
    int b = blockIdx.x * 8 + (threadIdx.x >> 5);
    int lane = threadIdx.x & 31;
    float p = 0.f;
    for (int k = lane; k < KG; k += 32) {
        float a;
        if (k < HH) a = g_ctxT[k * BB + b];
        else if (k < 2 * HH) a = g_hnewT[(k - HH) * BB + b];
        else a = g_xeT[(k - 2 * HH) * BB + b];
        p = fmaf(a, genw[k], p);
    }
#pragma unroll
    for (int o = 16; o; o >>= 1) p += __shfl_xor_sync(~0u, p, o);
    if (lane == 0) g_pgen[b] = fast_sigm(p + genb[0]);
}

// ---------------- output GEMM + p_gen scaling --------------------------------
// out[b,v] = p_gen[b] * (out_cat[b] . out_w[v] + out_b[v])
// BM=64, BN=128, BK=16, 128 threads, per-thread 8(m) x 8(n), f32x2 FMAs
__global__ void __launch_bounds__(128) k_outgemm(const float* __restrict__ outw,
                                                 const float* __restrict__ outb,
                                                 float* __restrict__ out) {
    __shared__ float As[16][64];
    __shared__ float Bs[16][128];
    int t = threadIdx.x;
    int nb = blockIdx.x * 128;
    int j = t & 15, i = t >> 4;
    int m0 = i * 8, n0 = j * 8;

    ull acc[8][4];
#pragma unroll
    for (int a = 0; a < 8; a++)
#pragma unroll
        for (int p = 0; p < 4; p++) acc[a][p] = pack2(0.f, 0.f);

    int vrow = nb + t;
    bool vok = vrow < VOCAB;
    const float4* wrow = reinterpret_cast<const float4*>(outw + (size_t)vrow * KOUT);

    for (int k0 = 0; k0 < KOUT; k0 += 16) {
#pragma unroll
        for (int q = 0; q < 8; q++) {
            int idx = t * 8 + q;
            int kk = idx >> 6, mm = idx & 63;
            int k = k0 + kk;
            As[kk][mm] = (k < HH) ? g_hnewT[k * BB + mm] : g_ctxT[(k - HH) * BB + mm];
        }
#pragma unroll
        for (int g = 0; g < 4; g++) {
            float4 v = vok ? wrow[(k0 >> 2) + g] : make_float4(0.f, 0.f, 0.f, 0.f);
            Bs[g * 4 + 0][t] = v.x; Bs[g * 4 + 1][t] = v.y;
            Bs[g * 4 + 2][t] = v.z; Bs[g * 4 + 3][t] = v.w;
        }
        __syncthreads();
#pragma unroll
        for (int kk = 0; kk < 16; kk++) {
            float4 a0 = *reinterpret_cast<const float4*>(&As[kk][m0]);
            float4 a1 = *reinterpret_cast<const float4*>(&As[kk][m0 + 4]);
            ull ad[8] = {pack2(a0.x, a0.x), pack2(a0.y, a0.y),
                         pack2(a0.z, a0.z), pack2(a0.w, a0.w),
                         pack2(a1.x, a1.x), pack2(a1.y, a1.y),
                         pack2(a1.z, a1.z), pack2(a1.w, a1.w)};
            const ull* br = reinterpret_cast<const ull*>(&Bs[kk][n0]);
            ull bv[4] = {br[0], br[1], br[2], br[3]};
#pragma unroll
            for (int mm = 0; mm < 8; mm++)
#pragma unroll
                for (int p = 0; p < 4; p++) fma2(acc[mm][p], ad[mm], bv[p]);
        }
        __syncthreads();
    }
#pragma unroll
    for (int mm = 0; mm < 8; mm++) {
        int b_ = m0 + mm;
        float pg = g_pgen[b_];
#pragma unroll
        for (int p = 0; p < 4; p++) {
            float lo, hi;
            unpack2(acc[mm][p], lo, hi);
            int v = nb + n0 + 2 * p;
            if (v < VOCAB)     out[(size_t)b_ * VOCAB + v]     = pg * (lo + outb[v]);
            if (v + 1 < VOCAB) out[(size_t)b_ * VOCAB + v + 1] = pg * (hi + outb[v + 1]);
        }
    }
}

// ---------------- pointer scatter (set semantics: last duplicate wins) -------
__global__ void k_scatter(const int* __restrict__ text, float* __restrict__ out) {
    __shared__ int sv[SS];
    __shared__ float sw[SS];
    int b = blockIdx.x, t = threadIdx.x;
    for (int s = t; s < SS; s += 256) {
        sv[s] = text[b * SS + s];
        sw[s] = g_attw[b * SS + s];
    }
    __syncthreads();
    float pptr = 1.f - g_pgen[b];
    for (int s = t; s < SS; s += 256) {
        int v = sv[s];
        bool last = true;
        for (int s2 = s + 1; s2 < SS; s2++)
            if (sv[s2] == v) { last = false; break; }
        if (last) out[(size_t)b * VOCAB + v] += pptr * sw[s];
    }
}

// ---------------- launch ------------------------------------------------------
extern "C" void kernel_launch(void* const* d_in, const int* in_sizes, int n_in,
                              void* d_out, int out_size) {
    // batch_size scalar may or may not be materialized as input #5
    int sh = (n_in >= 17 && in_sizes[5] == 1) ? 1 : 0;
    const int*   x    = (const int*)  d_in[0];
    const float* enc  = (const float*)d_in[1];
    const float* h0   = (const float*)d_in[2];
    const float* c0   = (const float*)d_in[3];
    const int*   text = (const int*)  d_in[4];
    const float* emb  = (const float*)d_in[5 + sh];
    const float* Vw   = (const float*)d_in[6 + sh];
    const float* Vb   = (const float*)d_in[7 + sh];
    const float* genw = (const float*)d_in[8 + sh];
    const float* genb = (const float*)d_in[9 + sh];
    const float* outw = (const float*)d_in[10 + sh];
    const float* outb = (const float*)d_in[11 + sh];
    const float* Wih  = (const float*)d_in[12 + sh];
    const float* Whh  = (const float*)d_in[13 + sh];
    const float* bih  = (const float*)d_in[14 + sh];
    const float* bhh  = (const float*)d_in[15 + sh];
    float* out = (float*)d_out;

    k_embed<<<75, 256>>>(x, emb);
    k_attn<<<64, 256>>>(enc, h0, Vw, Vb);
    k_gbias<<<512, 256>>>(bih, bhh);
    dim3 gg(16, 8);
    k_gates<<<gg, 256>>>(Wih, Whh);
    k_lstm<<<128, 256>>>(c0, out);
    k_pgen<<<8, 256>>>(genw, genb);
    k_outgemm<<<391, 128>>>(outw, outb, out);
    k_scatter<<<64, 256>>>(text, out);
}

// round 4
// speedup vs baseline: 1.3871x; 1.3871x over previous
#include <cuda_runtime.h>
#include <cstdint>

#define BB 64
#define SS 400
#define HH 512
#define EE 300
#define VOCAB 50000
#define KOUT 1024
#define KG   1324
#define GR   2048

#define OUT_H_OFF (BB * VOCAB)
#define OUT_C_OFF (BB * VOCAB + BB * HH)

// ---------------- scratch ----------------------------------------------------
__device__ float g_attw[BB * SS];
__device__ float g_xeT[EE * BB];
__device__ float g_ctxT[HH * BB];
__device__ float g_hprevT[HH * BB];
__device__ float g_hnewT[HH * BB];
__device__ float g_gates[BB * GR];
__device__ float g_pgen[BB];
__device__ float g_outcat[BB * KOUT];   // [b][k]  k<512: h_new, k>=512: ctx

typedef unsigned long long ull;

__device__ __forceinline__ ull pack2(float lo, float hi) {
    ull r; asm("mov.b64 %0,{%1,%2};" : "=l"(r) : "f"(lo), "f"(hi)); return r;
}
__device__ __forceinline__ void unpack2(ull v, float& lo, float& hi) {
    asm("mov.b64 {%0,%1},%2;" : "=f"(lo), "=f"(hi) : "l"(v));
}
__device__ __forceinline__ void fma2(ull& d, ull a, ull b) {
    asm("fma.rn.f32x2 %0,%1,%2,%3;" : "=l"(d) : "l"(a), "l"(b), "l"(d));
}
__device__ __forceinline__ float fast_tanh(float x) {
    float e = __expf(x + x);
    return 1.f - __fdividef(2.f, e + 1.f);
}
__device__ __forceinline__ float fast_sigm(float x) {
    return __fdividef(1.f, 1.f + __expf(-x));
}
__device__ __forceinline__ uint32_t f2tf32(float x) {
    uint32_t r; asm("cvt.rna.tf32.f32 %0, %1;" : "=r"(r) : "f"(x)); return r;
}
// D += A(16x8 tf32) * B(8x8 tf32), row.col
__device__ __forceinline__ void mma_tf32(float* d, const uint32_t* a, const uint32_t* b) {
    asm volatile("mma.sync.aligned.m16n8k8.row.col.f32.tf32.tf32.f32 "
                 "{%0,%1,%2,%3}, {%4,%5,%6,%7}, {%8,%9}, {%0,%1,%2,%3};"
                 : "+f"(d[0]), "+f"(d[1]), "+f"(d[2]), "+f"(d[3])
                 : "r"(a[0]), "r"(a[1]), "r"(a[2]), "r"(a[3]),
                   "r"(b[0]), "r"(b[1]));
}

// ---------------- embedding gather -------------------------------------------
__global__ void k_embed(const int* __restrict__ x, const float* __restrict__ emb) {
    int t = threadIdx.x;
    int b = t & 63;
    int e = blockIdx.x * 4 + (t >> 6);
    if (e < EE) g_xeT[e * BB + b] = emb[(size_t)x[b] * EE + e];
}

// ---------------- attention ---------------------------------------------------
__global__ void k_attn(const float* __restrict__ enc, const float* __restrict__ h0,
                       const float* __restrict__ Vw, const float* __restrict__ Vb) {
    __shared__ float sh_h[HH];
    __shared__ float sh_vw[HH];
    __shared__ float sh_sc[SS];
    __shared__ float sh_red[8];

    int b = blockIdx.x;
    int t = threadIdx.x;
    int lane = t & 31, w = t >> 5;

    for (int i = t; i < HH; i += 256) {
        float hv = h0[b * HH + i];
        sh_h[i] = hv;
        g_hprevT[i * BB + b] = hv;
        sh_vw[i] = Vw[i];
    }
    __syncthreads();

    const float* encb = enc + (size_t)b * (SS * HH);
    float vb = Vb[0];

    for (int s = w; s < SS; s += 8) {
        const float* row = encb + s * HH;
        float p = 0.f;
#pragma unroll
        for (int j = 0; j < 16; j++) {
            int h = j * 32 + lane;
            p += fast_tanh(row[h] + sh_h[h]) * sh_vw[h];
        }
#pragma unroll
        for (int o = 16; o; o >>= 1) p += __shfl_xor_sync(~0u, p, o);
        if (lane == 0) sh_sc[s] = p + vb;
    }
    __syncthreads();

    float m = -3.4e38f;
    for (int s = t; s < SS; s += 256) m = fmaxf(m, sh_sc[s]);
#pragma unroll
    for (int o = 16; o; o >>= 1) m = fmaxf(m, __shfl_xor_sync(~0u, m, o));
    if (lane == 0) sh_red[w] = m;
    __syncthreads();
    m = sh_red[0];
#pragma unroll
    for (int i = 1; i < 8; i++) m = fmaxf(m, sh_red[i]);
    __syncthreads();

    float ssum = 0.f;
    for (int s = t; s < SS; s += 256) {
        float e = __expf(sh_sc[s] - m);
        sh_sc[s] = e;
        ssum += e;
    }
#pragma unroll
    for (int o = 16; o; o >>= 1) ssum += __shfl_xor_sync(~0u, ssum, o);
    if (lane == 0) sh_red[w] = ssum;
    __syncthreads();
    ssum = 0.f;
#pragma unroll
    for (int i = 0; i < 8; i++) ssum += sh_red[i];
    float inv = 1.f / ssum;

    for (int s = t; s < SS; s += 256) {
        float wv = sh_sc[s] * inv;
        sh_sc[s] = wv;
        g_attw[b * SS + s] = wv;
    }
    __syncthreads();

    float a0 = 0.f, a1 = 0.f;
#pragma unroll 4
    for (int s = 0; s < SS; s++) {
        float wv = sh_sc[s];
        a0 = fmaf(wv, encb[s * HH + t], a0);
        a1 = fmaf(wv, encb[s * HH + t + 256], a1);
    }
    g_ctxT[t * BB + b] = a0;
    g_ctxT[(t + 256) * BB + b] = a1;
    g_outcat[b * KOUT + 512 + t] = a0;
    g_outcat[b * KOUT + 512 + t + 256] = a1;
}

// ---------------- gate bias init ----------------------------------------------
__global__ void k_gbias(const float* __restrict__ bih, const float* __restrict__ bhh) {
    int idx = blockIdx.x * 256 + threadIdx.x;
    if (idx < BB * GR) {
        int r = idx & (GR - 1);
        g_gates[idx] = bih[r] + bhh[r];
    }
}

// ---------------- gates GEMM (split-K x16) -------------------------------------
__global__ void __launch_bounds__(256) k_gates(const float* __restrict__ Wih,
                                               const float* __restrict__ Whh) {
    __shared__ float As[16][64];
    __shared__ float Bs[16][128];
    int t = threadIdx.x;
    int r0 = blockIdx.x * 128;     // grid.x = 16
    int kbase = blockIdx.y * 96;   // grid.y = 16 -> covers 1536 >= 1324
    int j = t & 15, i = t >> 4;
    int m0 = i * 4, n0 = j * 8;

    ull acc[4][4];
#pragma unroll
    for (int a = 0; a < 4; a++)
#pragma unroll
        for (int p = 0; p < 4; p++) acc[a][p] = pack2(0.f, 0.f);

    int rl = t & 127, kh = t >> 7;
    int r = r0 + rl;

    for (int k0 = kbase; k0 < kbase + 96; k0 += 16) {
#pragma unroll
        for (int q = 0; q < 4; q++) {
            int idx = t * 4 + q;
            int kk = idx >> 6, mm = idx & 63;
            int k = k0 + kk;
            float v;
            if (k >= KG) v = 0.f;
            else if (k < EE) v = g_xeT[k * BB + mm];
            else if (k < EE + HH) v = g_ctxT[(k - EE) * BB + mm];
            else v = g_hprevT[(k - EE - HH) * BB + mm];
            As[kk][mm] = v;
        }
#pragma unroll
        for (int g = 0; g < 2; g++) {
            int k = k0 + kh * 8 + g * 4;
            float4 v;
            if (k + 3 < 812) {
                v = *reinterpret_cast<const float4*>(Wih + (size_t)r * 812 + k);
            } else if (k >= 812 && k + 3 < KG) {
                v = *reinterpret_cast<const float4*>(Whh + (size_t)r * 512 + (k - 812));
            } else {
                float tmp[4];
#pragma unroll
                for (int q = 0; q < 4; q++) {
                    int kq = k + q;
                    tmp[q] = (kq < 812) ? Wih[(size_t)r * 812 + kq]
                           : (kq < KG) ? Whh[(size_t)r * 512 + (kq - 812)] : 0.f;
                }
                v = make_float4(tmp[0], tmp[1], tmp[2], tmp[3]);
            }
            int kk = kh * 8 + g * 4;
            Bs[kk + 0][rl] = v.x; Bs[kk + 1][rl] = v.y;
            Bs[kk + 2][rl] = v.z; Bs[kk + 3][rl] = v.w;
        }
        __syncthreads();
#pragma unroll
        for (int kk = 0; kk < 16; kk++) {
            float4 a4 = *reinterpret_cast<const float4*>(&As[kk][m0]);
            ull ad[4] = {pack2(a4.x, a4.x), pack2(a4.y, a4.y),
                         pack2(a4.z, a4.z), pack2(a4.w, a4.w)};
            const ull* br = reinterpret_cast<const ull*>(&Bs[kk][n0]);
            ull bv[4] = {br[0], br[1], br[2], br[3]};
#pragma unroll
            for (int mm = 0; mm < 4; mm++)
#pragma unroll
                for (int p = 0; p < 4; p++) fma2(acc[mm][p], ad[mm], bv[p]);
        }
        __syncthreads();
    }
#pragma unroll
    for (int mm = 0; mm < 4; mm++) {
        int b_ = m0 + mm;
#pragma unroll
        for (int p = 0; p < 4; p++) {
            float lo, hi;
            unpack2(acc[mm][p], lo, hi);
            int rr = r0 + n0 + 2 * p;
            atomicAdd(&g_gates[b_ * GR + rr], lo);
            atomicAdd(&g_gates[b_ * GR + rr + 1], hi);
        }
    }
}

// ---------------- LSTM elementwise ---------------------------------------------
__global__ void k_lstm(const float* __restrict__ c0, float* __restrict__ out) {
    int idx = blockIdx.x * 256 + threadIdx.x;
    int b = idx >> 9, h = idx & (HH - 1);
    const float* g = g_gates + b * GR;
    float gi = g[h], gf = g[HH + h], gg = g[2 * HH + h], go = g[3 * HH + h];
    float c = fast_sigm(gf) * c0[idx] + fast_sigm(gi) * fast_tanh(gg);
    float hn = fast_sigm(go) * fast_tanh(c);
    out[OUT_H_OFF + idx] = hn;
    out[OUT_C_OFF + idx] = c;
    g_hnewT[h * BB + b] = hn;
    g_outcat[b * KOUT + h] = hn;
}

// ---------------- p_gen ---------------------------------------------------------
__global__ void k_pgen(const float* __restrict__ genw, const float* __restrict__ genb) {
    int b = blockIdx.x * 8 + (threadIdx.x >> 5);
    int lane = threadIdx.x & 31;
    float p = 0.f;
    for (int k = lane; k < KG; k += 32) {
        float a;
        if (k < HH) a = g_ctxT[k * BB + b];
        else if (k < 2 * HH) a = g_hnewT[(k - HH) * BB + b];
        else a = g_xeT[(k - 2 * HH) * BB + b];
        p = fmaf(a, genw[k], p);
    }
#pragma unroll
    for (int o = 16; o; o >>= 1) p += __shfl_xor_sync(~0u, p, o);
    if (lane == 0) g_pgen[b] = fast_sigm(p + genb[0]);
}

// ---------------- output GEMM: tf32 mma.sync, M=64 N=128 K=1024 -----------------
// 8 warps in 2(m) x 4(n); each warp: 2 m16 x 4 n8 fragments; BK=32.
#define LDPAD 36
__global__ void __launch_bounds__(256) k_outgemm(const float* __restrict__ outw,
                                                 const float* __restrict__ outb,
                                                 float* __restrict__ out) {
    __shared__ uint32_t sA[64 * LDPAD];
    __shared__ uint32_t sB[128 * LDPAD];

    int t = threadIdx.x;
    int wid = t >> 5, lane = t & 31;
    int gid = lane >> 2, tig = lane & 3;
    int nb = blockIdx.x * 128;
    int m0 = (wid & 1) * 32;
    int n0 = (wid >> 1) * 32;

    float acc[2][4][4];
#pragma unroll
    for (int mt = 0; mt < 2; mt++)
#pragma unroll
        for (int nt = 0; nt < 4; nt++)
#pragma unroll
            for (int p = 0; p < 4; p++) acc[mt][nt][p] = 0.f;

    for (int kc = 0; kc < 32; kc++) {
        int kbase = kc * 32;
        // A tile: 64 x 32 = 512 float4
#pragma unroll
        for (int q = 0; q < 2; q++) {
            int i = q * 256 + t;
            int row = i >> 3, c4 = i & 7;
            float4 v = *reinterpret_cast<const float4*>(
                g_outcat + (size_t)row * KOUT + kbase + c4 * 4);
            uint32_t* d = &sA[row * LDPAD + c4 * 4];
            d[0] = f2tf32(v.x); d[1] = f2tf32(v.y);
            d[2] = f2tf32(v.z); d[3] = f2tf32(v.w);
        }
        // B tile: 128 x 32 = 1024 float4
#pragma unroll
        for (int q = 0; q < 4; q++) {
            int i = q * 256 + t;
            int row = i >> 3, c4 = i & 7;
            int vrow = nb + row;
            float4 v = make_float4(0.f, 0.f, 0.f, 0.f);
            if (vrow < VOCAB)
                v = *reinterpret_cast<const float4*>(
                    outw + (size_t)vrow * KOUT + kbase + c4 * 4);
            uint32_t* d = &sB[row * LDPAD + c4 * 4];
            d[0] = f2tf32(v.x); d[1] = f2tf32(v.y);
            d[2] = f2tf32(v.z); d[3] = f2tf32(v.w);
        }
        __syncthreads();

#pragma unroll
        for (int ks = 0; ks < 4; ks++) {
            int kb = ks * 8;
            uint32_t a[2][4], b[4][2];
#pragma unroll
            for (int mt = 0; mt < 2; mt++) {
                int r = m0 + mt * 16 + gid;
                a[mt][0] = sA[r * LDPAD + kb + tig];
                a[mt][1] = sA[(r + 8) * LDPAD + kb + tig];
                a[mt][2] = sA[r * LDPAD + kb + tig + 4];
                a[mt][3] = sA[(r + 8) * LDPAD + kb + tig + 4];
            }
#pragma unroll
            for (int nt = 0; nt < 4; nt++) {
                int rn = n0 + nt * 8 + gid;
                b[nt][0] = sB[rn * LDPAD + kb + tig];
                b[nt][1] = sB[rn * LDPAD + kb + tig + 4];
            }
#pragma unroll
            for (int mt = 0; mt < 2; mt++)
#pragma unroll
                for (int nt = 0; nt < 4; nt++)
                    mma_tf32(acc[mt][nt], a[mt], b[nt]);
        }
        __syncthreads();
    }

    // epilogue: c0,c1 -> (row, 2tig..2tig+1); c2,c3 -> (row+8, same)
#pragma unroll
    for (int mt = 0; mt < 2; mt++) {
        int r = m0 + mt * 16 + gid;
        float pg0 = g_pgen[r], pg1 = g_pgen[r + 8];
#pragma unroll
        for (int nt = 0; nt < 4; nt++) {
            int v0 = nb + n0 + nt * 8 + 2 * tig;
            if (v0 < VOCAB) {
                float2 ob = *reinterpret_cast<const float2*>(outb + v0);
                float2 o0, o1;
                o0.x = pg0 * (acc[mt][nt][0] + ob.x);
                o0.y = pg0 * (acc[mt][nt][1] + ob.y);
                o1.x = pg1 * (acc[mt][nt][2] + ob.x);
                o1.y = pg1 * (acc[mt][nt][3] + ob.y);
                *reinterpret_cast<float2*>(out + (size_t)r * VOCAB + v0) = o0;
                *reinterpret_cast<float2*>(out + (size_t)(r + 8) * VOCAB + v0) = o1;
            }
        }
    }
}

// ---------------- pointer scatter ----------------------------------------------
__global__ void k_scatter(const int* __restrict__ text, float* __restrict__ out) {
    __shared__ int sv[SS];
    __shared__ float sw[SS];
    int b = blockIdx.x, t = threadIdx.x;
    for (int s = t; s < SS; s += 256) {
        sv[s] = text[b * SS + s];
        sw[s] = g_attw[b * SS + s];
    }
    __syncthreads();
    float pptr = 1.f - g_pgen[b];
    for (int s = t; s < SS; s += 256) {
        int v = sv[s];
        bool last = true;
        for (int s2 = s + 1; s2 < SS; s2++)
            if (sv[s2] == v) { last = false; break; }
        if (last) out[(size_t)b * VOCAB + v] += pptr * sw[s];
    }
}

// ---------------- launch --------------------------------------------------------
extern "C" void kernel_launch(void* const* d_in, const int* in_sizes, int n_in,
                              void* d_out, int out_size) {
    int sh = (n_in >= 17 && in_sizes[5] == 1) ? 1 : 0;
    const int*   x    = (const int*)  d_in[0];
    const float* enc  = (const float*)d_in[1];
    const float* h0   = (const float*)d_in[2];
    const float* c0   = (const float*)d_in[3];
    const int*   text = (const int*)  d_in[4];
    const float* emb  = (const float*)d_in[5 + sh];
    const float* Vw   = (const float*)d_in[6 + sh];
    const float* Vb   = (const float*)d_in[7 + sh];
    const float* genw = (const float*)d_in[8 + sh];
    const float* genb = (const float*)d_in[9 + sh];
    const float* outw = (const float*)d_in[10 + sh];
    const float* outb = (const float*)d_in[11 + sh];
    const float* Wih  = (const float*)d_in[12 + sh];
    const float* Whh  = (const float*)d_in[13 + sh];
    const float* bih  = (const float*)d_in[14 + sh];
    const float* bhh  = (const float*)d_in[15 + sh];
    float* out = (float*)d_out;

    k_embed<<<75, 256>>>(x, emb);
    k_attn<<<64, 256>>>(enc, h0, Vw, Vb);
    k_gbias<<<512, 256>>>(bih, bhh);
    dim3 gg(16, 16);
    k_gates<<<gg, 256>>>(Wih, Whh);
    k_lstm<<<128, 256>>>(c0, out);
    k_pgen<<<8, 256>>>(genw, genb);
    k_outgemm<<<391, 256>>>(outw, outb, out);
    k_scatter<<<64, 256>>>(text, out);
}

// round 5
// speedup vs baseline: 1.9547x; 1.4092x over previous
#include <cuda_runtime.h>
#include <cstdint>

#define BB 64
#define SS 400
#define HH 512
#define EE 300
#define VOCAB 50000
#define KOUT 1024
#define KG   1324
#define KPAD 1536
#define GR   2048

#define OUT_H_OFF (BB * VOCAB)
#define OUT_C_OFF (BB * VOCAB + BB * HH)

// ---------------- scratch ----------------------------------------------------
__device__ float g_attw[BB * SS];
__device__ float g_score[BB * SS];
__device__ float g_gcat[BB * KPAD];     // [b][k]: xe(0..299) | ctx(300..811) | hprev(812..1323) | 0-pad
__device__ float g_outcat[BB * KOUT];   // [b][k]: h_new(0..511) | ctx(512..1023)
__device__ float g_gates[BB * GR];
__device__ float g_pgen[BB];

__device__ __forceinline__ float fast_tanh(float x) {
    float e = __expf(x + x);
    return 1.f - __fdividef(2.f, e + 1.f);
}
__device__ __forceinline__ float fast_sigm(float x) {
    return __fdividef(1.f, 1.f + __expf(-x));
}
__device__ __forceinline__ uint32_t f2tf32(float x) {
    uint32_t r; asm("cvt.rna.tf32.f32 %0, %1;" : "=r"(r) : "f"(x)); return r;
}
__device__ __forceinline__ void mma_tf32(float* d, const uint32_t* a, const uint32_t* b) {
    asm volatile("mma.sync.aligned.m16n8k8.row.col.f32.tf32.tf32.f32 "
                 "{%0,%1,%2,%3}, {%4,%5,%6,%7}, {%8,%9}, {%0,%1,%2,%3};"
                 : "+f"(d[0]), "+f"(d[1]), "+f"(d[2]), "+f"(d[3])
                 : "r"(a[0]), "r"(a[1]), "r"(a[2]), "r"(a[3]),
                   "r"(b[0]), "r"(b[1]));
}
__device__ __forceinline__ uint32_t smem_u32(const void* p) {
    uint32_t a;
    asm("{ .reg .u64 t; cvta.to.shared.u64 t, %1; cvt.u32.u64 %0, t; }" : "=r"(a) : "l"(p));
    return a;
}
__device__ __forceinline__ void cp_async16(uint32_t dst, const void* src, int src_bytes) {
    asm volatile("cp.async.cg.shared.global [%0], [%1], 16, %2;"
                 :: "r"(dst), "l"(src), "r"(src_bytes) : "memory");
}
#define CP_COMMIT() asm volatile("cp.async.commit_group;" ::: "memory")
#define CP_WAIT(n)  asm volatile("cp.async.wait_group %0;" :: "n"(n) : "memory")

extern __shared__ float dynsmem[];

// ---------------- embedding gather -------------------------------------------
__global__ void k_embed(const int* __restrict__ x, const float* __restrict__ emb) {
    int t = threadIdx.x;
    int b = t & 63;
    int e = blockIdx.x * 4 + (t >> 6);
    if (e < EE) g_gcat[b * KPAD + e] = emb[(size_t)x[b] * EE + e];
}

// ---------------- attention scores (grid 64 x 2) ------------------------------
__global__ void k_score(const float* __restrict__ enc, const float* __restrict__ h0,
                        const float* __restrict__ Vw, const float* __restrict__ Vb) {
    __shared__ float sh_h[HH];
    __shared__ float sh_vw[HH];
    int b = blockIdx.x, half = blockIdx.y;
    int t = threadIdx.x;
    int lane = t & 31, w = t >> 5;

    for (int i = t; i < HH; i += 256) {
        float hv = h0[b * HH + i];
        sh_h[i] = hv;
        sh_vw[i] = Vw[i];
        if (half == 0) g_gcat[b * KPAD + 812 + i] = hv;   // stage h_prev
    }
    __syncthreads();

    const float* encb = enc + (size_t)b * (SS * HH);
    float vb = Vb[0];
    int s0 = half * 200;
    for (int s = s0 + w; s < s0 + 200; s += 8) {
        const float* row = encb + s * HH;
        float p = 0.f;
#pragma unroll
        for (int j = 0; j < 16; j++) {
            int h = j * 32 + lane;
            p += fast_tanh(row[h] + sh_h[h]) * sh_vw[h];
        }
#pragma unroll
        for (int o = 16; o; o >>= 1) p += __shfl_xor_sync(~0u, p, o);
        if (lane == 0) g_score[b * SS + s] = p + vb;
    }
}

// ---------------- softmax + ctx (grid 64 x 2, h-halves) ------------------------
__global__ void k_ctx(const float* __restrict__ enc) {
    __shared__ float sh_w[SS];
    __shared__ float sh_red[8];
    int b = blockIdx.x, hh = blockIdx.y;
    int t = threadIdx.x;
    int lane = t & 31, w = t >> 5;

    for (int s = t; s < SS; s += 256) sh_w[s] = g_score[b * SS + s];
    __syncthreads();

    float m = -3.4e38f;
    for (int s = t; s < SS; s += 256) m = fmaxf(m, sh_w[s]);
#pragma unroll
    for (int o = 16; o; o >>= 1) m = fmaxf(m, __shfl_xor_sync(~0u, m, o));
    if (lane == 0) sh_red[w] = m;
    __syncthreads();
    m = sh_red[0];
#pragma unroll
    for (int i = 1; i < 8; i++) m = fmaxf(m, sh_red[i]);
    __syncthreads();

    float ssum = 0.f;
    for (int s = t; s < SS; s += 256) {
        float e = __expf(sh_w[s] - m);
        sh_w[s] = e;
        ssum += e;
    }
#pragma unroll
    for (int o = 16; o; o >>= 1) ssum += __shfl_xor_sync(~0u, ssum, o);
    if (lane == 0) sh_red[w] = ssum;
    __syncthreads();
    ssum = 0.f;
#pragma unroll
    for (int i = 0; i < 8; i++) ssum += sh_red[i];
    float inv = 1.f / ssum;
    __syncthreads();

    for (int s = t; s < SS; s += 256) {
        float wv = sh_w[s] * inv;
        sh_w[s] = wv;
        if (hh == 0) g_attw[b * SS + s] = wv;
    }
    __syncthreads();

    // ctx for h = hh*256 + t
    int h = hh * 256 + t;
    const float* encb = enc + (size_t)b * (SS * HH) + h;
    float a = 0.f;
#pragma unroll 4
    for (int s = 0; s < SS; s++) a = fmaf(sh_w[s], encb[s * HH], a);
    g_outcat[b * KOUT + 512 + h] = a;
    g_gcat[b * KPAD + 300 + h] = a;
}

// ---------------- gate bias init ----------------------------------------------
__global__ void k_gbias(const float* __restrict__ bih, const float* __restrict__ bhh) {
    int idx = blockIdx.x * 256 + threadIdx.x;
    if (idx < BB * GR) {
        int r = idx & (GR - 1);
        g_gates[idx] = bih[r] + bhh[r];
    }
}

// ---------------- gates GEMM: tf32 mma + cp.async 2-stage ----------------------
// grid (16, 8): x = N-tile (128 gate rows), y = split-K (6 chunks of 32 each).
#define GP 36
#define G_ASZ (64 * GP)
#define G_BSZ (128 * GP)
#define G_STG (G_ASZ + G_BSZ)
__global__ void __launch_bounds__(256) k_gates(const float* __restrict__ Wih,
                                               const float* __restrict__ Whh) {
    int t = threadIdx.x;
    int wid = t >> 5, lane = t & 31;
    int gid = lane >> 2, tig = lane & 3;
    int r0 = blockIdx.x * 128;
    int cbase = blockIdx.y * 6;      // chunk index base (48 chunks of 32 cover KPAD)
    int m0 = (wid & 1) * 32;
    int n0 = (wid >> 1) * 32;
    uint32_t smb = smem_u32(dynsmem);

    float acc[2][4][4];
#pragma unroll
    for (int mt = 0; mt < 2; mt++)
#pragma unroll
        for (int nt = 0; nt < 4; nt++)
#pragma unroll
            for (int p = 0; p < 4; p++) acc[mt][nt][p] = 0.f;

    // stage issue: chunk c -> stage s
#define G_ISSUE(s, c) do {                                                         \
        uint32_t sa = smb + (s) * G_STG * 4;                                       \
        uint32_t sb = sa + G_ASZ * 4;                                              \
        int kbase = (c) * 32;                                                      \
        _Pragma("unroll")                                                          \
        for (int q = 0; q < 2; q++) {                                              \
            int i = q * 256 + t, row = i >> 3, c4 = i & 7;                         \
            cp_async16(sa + (row * GP + c4 * 4) * 4,                               \
                       g_gcat + (size_t)row * KPAD + kbase + c4 * 4, 16);          \
        }                                                                          \
        _Pragma("unroll")                                                          \
        for (int q = 0; q < 4; q++) {                                              \
            int i = q * 256 + t, row = i >> 3, c4 = i & 7;                         \
            int gr = r0 + row, k = kbase + c4 * 4;                                 \
            const float* src; int sz = 16;                                         \
            if (k < 812)       src = Wih + (size_t)gr * 812 + k;                   \
            else if (k < KG)   src = Whh + (size_t)gr * 512 + (k - 812);           \
            else             { src = Whh; sz = 0; }                                \
            cp_async16(sb + (row * GP + c4 * 4) * 4, src, sz);                     \
        }                                                                          \
        CP_COMMIT();                                                               \
    } while (0)

    G_ISSUE(0, cbase);
    for (int j = 0; j < 6; j++) {
        if (j + 1 < 6) G_ISSUE((j + 1) & 1, cbase + j + 1); else CP_COMMIT();
        CP_WAIT(1);
        __syncthreads();
        const float* sA = dynsmem + (j & 1) * G_STG;
        const float* sB = sA + G_ASZ;
#pragma unroll
        for (int ks = 0; ks < 4; ks++) {
            int kb = ks * 8;
            uint32_t a[2][4], b[4][2];
#pragma unroll
            for (int mt = 0; mt < 2; mt++) {
                int r = m0 + mt * 16 + gid;
                a[mt][0] = f2tf32(sA[r * GP + kb + tig]);
                a[mt][1] = f2tf32(sA[(r + 8) * GP + kb + tig]);
                a[mt][2] = f2tf32(sA[r * GP + kb + tig + 4]);
                a[mt][3] = f2tf32(sA[(r + 8) * GP + kb + tig + 4]);
            }
#pragma unroll
            for (int nt = 0; nt < 4; nt++) {
                int rn = n0 + nt * 8 + gid;
                b[nt][0] = f2tf32(sB[rn * GP + kb + tig]);
                b[nt][1] = f2tf32(sB[rn * GP + kb + tig + 4]);
            }
#pragma unroll
            for (int mt = 0; mt < 2; mt++)
#pragma unroll
                for (int nt = 0; nt < 4; nt++)
                    mma_tf32(acc[mt][nt], a[mt], b[nt]);
        }
        __syncthreads();
    }

#pragma unroll
    for (int mt = 0; mt < 2; mt++) {
        int r = m0 + mt * 16 + gid;
#pragma unroll
        for (int nt = 0; nt < 4; nt++) {
            int col = r0 + n0 + nt * 8 + 2 * tig;
            atomicAdd(&g_gates[r * GR + col],       acc[mt][nt][0]);
            atomicAdd(&g_gates[r * GR + col + 1],   acc[mt][nt][1]);
            atomicAdd(&g_gates[(r + 8) * GR + col],     acc[mt][nt][2]);
            atomicAdd(&g_gates[(r + 8) * GR + col + 1], acc[mt][nt][3]);
        }
    }
}

// ---------------- LSTM elementwise ---------------------------------------------
__global__ void k_lstm(const float* __restrict__ c0, float* __restrict__ out) {
    int idx = blockIdx.x * 256 + threadIdx.x;
    int b = idx >> 9, h = idx & (HH - 1);
    const float* g = g_gates + b * GR;
    float gi = g[h], gf = g[HH + h], gg = g[2 * HH + h], go = g[3 * HH + h];
    float c = fast_sigm(gf) * c0[idx] + fast_sigm(gi) * fast_tanh(gg);
    float hn = fast_sigm(go) * fast_tanh(c);
    out[OUT_H_OFF + idx] = hn;
    out[OUT_C_OFF + idx] = c;
    g_outcat[b * KOUT + h] = hn;
}

// ---------------- p_gen ---------------------------------------------------------
__global__ void k_pgen(const float* __restrict__ genw, const float* __restrict__ genb) {
    int b = blockIdx.x * 8 + (threadIdx.x >> 5);
    int lane = threadIdx.x & 31;
    float p = 0.f;
    for (int k = lane; k < KG; k += 32) {
        float a;
        if (k < HH) a = g_outcat[b * KOUT + 512 + k];          // ctx
        else if (k < 2 * HH) a = g_outcat[b * KOUT + (k - HH)]; // h_new
        else a = g_gcat[b * KPAD + (k - 2 * HH)];               // xe
        p = fmaf(a, genw[k], p);
    }
#pragma unroll
    for (int o = 16; o; o >>= 1) p += __shfl_xor_sync(~0u, p, o);
    if (lane == 0) g_pgen[b] = fast_sigm(p + genb[0]);
}

// ---------------- output GEMM: tf32 mma + cp.async 3-stage ---------------------
#define OP 36
#define O_ASZ (64 * OP)
#define O_BSZ (128 * OP)
#define O_STG (O_ASZ + O_BSZ)
__global__ void __launch_bounds__(256) k_outgemm(const float* __restrict__ outw,
                                                 const float* __restrict__ outb,
                                                 float* __restrict__ out) {
    int t = threadIdx.x;
    int wid = t >> 5, lane = t & 31;
    int gid = lane >> 2, tig = lane & 3;
    int nb = blockIdx.x * 128;
    int m0 = (wid & 1) * 32;
    int n0 = (wid >> 1) * 32;
    uint32_t smb = smem_u32(dynsmem);

    float acc[2][4][4];
#pragma unroll
    for (int mt = 0; mt < 2; mt++)
#pragma unroll
        for (int nt = 0; nt < 4; nt++)
#pragma unroll
            for (int p = 0; p < 4; p++) acc[mt][nt][p] = 0.f;

#define O_ISSUE(s, kc) do {                                                        \
        uint32_t sa = smb + (s) * O_STG * 4;                                       \
        uint32_t sb = sa + O_ASZ * 4;                                              \
        int kbase = (kc) * 32;                                                     \
        _Pragma("unroll")                                                          \
        for (int q = 0; q < 2; q++) {                                              \
            int i = q * 256 + t, row = i >> 3, c4 = i & 7;                         \
            cp_async16(sa + (row * OP + c4 * 4) * 4,                               \
                       g_outcat + (size_t)row * KOUT + kbase + c4 * 4, 16);        \
        }                                                                          \
        _Pragma("unroll")                                                          \
        for (int q = 0; q < 4; q++) {                                              \
            int i = q * 256 + t, row = i >> 3, c4 = i & 7;                         \
            int vr = nb + row;                                                     \
            const float* src = outw;                                               \
            int sz = 0;                                                            \
            if (vr < VOCAB) { src = outw + (size_t)vr * KOUT + kbase + c4 * 4; sz = 16; } \
            cp_async16(sb + (row * OP + c4 * 4) * 4, src, sz);                     \
        }                                                                          \
        CP_COMMIT();                                                               \
    } while (0)

    O_ISSUE(0, 0);
    O_ISSUE(1, 1);
    for (int kc = 0; kc < 32; kc++) {
        if (kc + 2 < 32) O_ISSUE((kc + 2) % 3, kc + 2); else CP_COMMIT();
        CP_WAIT(2);
        __syncthreads();
        const float* sA = dynsmem + (kc % 3) * O_STG;
        const float* sB = sA + O_ASZ;
#pragma unroll
        for (int ks = 0; ks < 4; ks++) {
            int kb = ks * 8;
            uint32_t a[2][4], b[4][2];
#pragma unroll
            for (int mt = 0; mt < 2; mt++) {
                int r = m0 + mt * 16 + gid;
                a[mt][0] = f2tf32(sA[r * OP + kb + tig]);
                a[mt][1] = f2tf32(sA[(r + 8) * OP + kb + tig]);
                a[mt][2] = f2tf32(sA[r * OP + kb + tig + 4]);
                a[mt][3] = f2tf32(sA[(r + 8) * OP + kb + tig + 4]);
            }
#pragma unroll
            for (int nt = 0; nt < 4; nt++) {
                int rn = n0 + nt * 8 + gid;
                b[nt][0] = f2tf32(sB[rn * OP + kb + tig]);
                b[nt][1] = f2tf32(sB[rn * OP + kb + tig + 4]);
            }
#pragma unroll
            for (int mt = 0; mt < 2; mt++)
#pragma unroll
                for (int nt = 0; nt < 4; nt++)
                    mma_tf32(acc[mt][nt], a[mt], b[nt]);
        }
        __syncthreads();
    }

#pragma unroll
    for (int mt = 0; mt < 2; mt++) {
        int r = m0 + mt * 16 + gid;
        float pg0 = g_pgen[r], pg1 = g_pgen[r + 8];
#pragma unroll
        for (int nt = 0; nt < 4; nt++) {
            int v0 = nb + n0 + nt * 8 + 2 * tig;
            if (v0 < VOCAB) {
                float2 ob = *reinterpret_cast<const float2*>(outb + v0);
                float2 o0, o1;
                o0.x = pg0 * (acc[mt][nt][0] + ob.x);
                o0.y = pg0 * (acc[mt][nt][1] + ob.y);
                o1.x = pg1 * (acc[mt][nt][2] + ob.x);
                o1.y = pg1 * (acc[mt][nt][3] + ob.y);
                *reinterpret_cast<float2*>(out + (size_t)r * VOCAB + v0) = o0;
                *reinterpret_cast<float2*>(out + (size_t)(r + 8) * VOCAB + v0) = o1;
            }
        }
    }
}

// ---------------- pointer scatter ----------------------------------------------
__global__ void k_scatter(const int* __restrict__ text, float* __restrict__ out) {
    __shared__ int sv[SS];
    __shared__ float sw[SS];
    int b = blockIdx.x, t = threadIdx.x;
    for (int s = t; s < SS; s += 256) {
        sv[s] = text[b * SS + s];
        sw[s] = g_attw[b * SS + s];
    }
    __syncthreads();
    float pptr = 1.f - g_pgen[b];
    for (int s = t; s < SS; s += 256) {
        int v = sv[s];
        bool last = true;
        for (int s2 = s + 1; s2 < SS; s2++)
            if (sv[s2] == v) { last = false; break; }
        if (last) out[(size_t)b * VOCAB + v] += pptr * sw[s];
    }
}

// ---------------- launch --------------------------------------------------------
extern "C" void kernel_launch(void* const* d_in, const int* in_sizes, int n_in,
                              void* d_out, int out_size) {
    int sh = (n_in >= 17 && in_sizes[5] == 1) ? 1 : 0;
    const int*   x    = (const int*)  d_in[0];
    const float* enc  = (const float*)d_in[1];
    const float* h0   = (const float*)d_in[2];
    const float* c0   = (const float*)d_in[3];
    const int*   text = (const int*)  d_in[4];
    const float* emb  = (const float*)d_in[5 + sh];
    const float* Vw   = (const float*)d_in[6 + sh];
    const float* Vb   = (const float*)d_in[7 + sh];
    const float* genw = (const float*)d_in[8 + sh];
    const float* genb = (const float*)d_in[9 + sh];
    const float* outw = (const float*)d_in[10 + sh];
    const float* outb = (const float*)d_in[11 + sh];
    const float* Wih  = (const float*)d_in[12 + sh];
    const float* Whh  = (const float*)d_in[13 + sh];
    const float* bih  = (const float*)d_in[14 + sh];
    const float* bhh  = (const float*)d_in[15 + sh];
    float* out = (float*)d_out;

    cudaFuncSetAttribute(k_outgemm, cudaFuncAttributeMaxDynamicSharedMemorySize,
                         3 * O_STG * 4);
    cudaFuncSetAttribute(k_gates, cudaFuncAttributeMaxDynamicSharedMemorySize,
                         2 * G_STG * 4);

    k_embed<<<75, 256>>>(x, emb);
    dim3 gs(64, 2);
    k_score<<<gs, 256>>>(enc, h0, Vw, Vb);
    k_ctx<<<gs, 256>>>(enc);
    k_gbias<<<512, 256>>>(bih, bhh);
    dim3 gg(16, 8);
    k_gates<<<gg, 256, 2 * G_STG * 4>>>(Wih, Whh);
    k_lstm<<<128, 256>>>(c0, out);
    k_pgen<<<8, 256>>>(genw, genb);
    k_outgemm<<<391, 256, 3 * O_STG * 4>>>(outw, outb, out);
    k_scatter<<<64, 256>>>(text, out);
}

// round 6
// speedup vs baseline: 2.0367x; 1.0419x over previous
#include <cuda_runtime.h>
#include <cstdint>

#define BB 64
#define SS 400
#define HH 512
#define EE 300
#define VOCAB 50000
#define KOUT 1024
#define KG   1324
#define KPAD 1536
#define GR   2048

#define OUT_H_OFF (BB * VOCAB)
#define OUT_C_OFF (BB * VOCAB + BB * HH)

// ---------------- scratch ----------------------------------------------------
__device__ float g_attw[BB * SS];
__device__ float g_score[BB * SS];
__device__ float g_gcat[BB * KPAD];     // [b][k]: xe | ctx | hprev | 0-pad (exact fp32)
__device__ float g_outcat[BB * KOUT];   // [b][k]: h_new | ctx  (pre-rounded to tf32 bits)
__device__ float g_gates[BB * GR];
__device__ float g_pgen[BB];

__device__ __forceinline__ float fast_tanh(float x) {
    float e = __expf(x + x);
    return 1.f - __fdividef(2.f, e + 1.f);
}
__device__ __forceinline__ float fast_sigm(float x) {
    return __fdividef(1.f, 1.f + __expf(-x));
}
__device__ __forceinline__ uint32_t f2tf32(float x) {
    uint32_t r; asm("cvt.rna.tf32.f32 %0, %1;" : "=r"(r) : "f"(x)); return r;
}
__device__ __forceinline__ float tf32r(float x) {   // value rounded to tf32 grid
    return __uint_as_float(f2tf32(x));
}
__device__ __forceinline__ void mma_tf32(float* d, const uint32_t* a, const uint32_t* b) {
    asm volatile("mma.sync.aligned.m16n8k8.row.col.f32.tf32.tf32.f32 "
                 "{%0,%1,%2,%3}, {%4,%5,%6,%7}, {%8,%9}, {%0,%1,%2,%3};"
                 : "+f"(d[0]), "+f"(d[1]), "+f"(d[2]), "+f"(d[3])
                 : "r"(a[0]), "r"(a[1]), "r"(a[2]), "r"(a[3]),
                   "r"(b[0]), "r"(b[1]));
}
__device__ __forceinline__ uint32_t smem_u32(const void* p) {
    uint32_t a;
    asm("{ .reg .u64 t; cvta.to.shared.u64 t, %1; cvt.u32.u64 %0, t; }" : "=r"(a) : "l"(p));
    return a;
}
__device__ __forceinline__ void cp_async16(uint32_t dst, const void* src, int src_bytes) {
    asm volatile("cp.async.cg.shared.global [%0], [%1], 16, %2;"
                 :: "r"(dst), "l"(src), "r"(src_bytes) : "memory");
}
#define CP_COMMIT() asm volatile("cp.async.commit_group;" ::: "memory")
#define CP_WAIT(n)  asm volatile("cp.async.wait_group %0;" :: "n"(n) : "memory")

extern __shared__ float dynsmem[];

// ---------------- embedding gather -------------------------------------------
__global__ void k_embed(const int* __restrict__ x, const float* __restrict__ emb) {
    int t = threadIdx.x;
    int b = t & 63;
    int e = blockIdx.x * 4 + (t >> 6);
    if (e < EE) g_gcat[b * KPAD + e] = emb[(size_t)x[b] * EE + e];
}

// ---------------- attention scores (grid 64 x 2) ------------------------------
__global__ void k_score(const float* __restrict__ enc, const float* __restrict__ h0,
                        const float* __restrict__ Vw, const float* __restrict__ Vb) {
    __shared__ float sh_h[HH];
    __shared__ float sh_vw[HH];
    int b = blockIdx.x, half = blockIdx.y;
    int t = threadIdx.x;
    int lane = t & 31, w = t >> 5;

    for (int i = t; i < HH; i += 256) {
        float hv = h0[b * HH + i];
        sh_h[i] = hv;
        sh_vw[i] = Vw[i];
        if (half == 0) g_gcat[b * KPAD + 812 + i] = hv;
    }
    __syncthreads();

    const float* encb = enc + (size_t)b * (SS * HH);
    float vb = Vb[0];
    int s0 = half * 200;
    for (int s = s0 + w; s < s0 + 200; s += 8) {
        const float* row = encb + s * HH;
        float p = 0.f;
#pragma unroll
        for (int j = 0; j < 16; j++) {
            int h = j * 32 + lane;
            p += fast_tanh(row[h] + sh_h[h]) * sh_vw[h];
        }
#pragma unroll
        for (int o = 16; o; o >>= 1) p += __shfl_xor_sync(~0u, p, o);
        if (lane == 0) g_score[b * SS + s] = p + vb;
    }
}

// ---------------- softmax + ctx (grid 64 x 2, h-halves) ------------------------
__global__ void k_ctx(const float* __restrict__ enc) {
    __shared__ float sh_w[SS];
    __shared__ float sh_red[8];
    int b = blockIdx.x, hh = blockIdx.y;
    int t = threadIdx.x;
    int lane = t & 31, w = t >> 5;

    for (int s = t; s < SS; s += 256) sh_w[s] = g_score[b * SS + s];
    __syncthreads();

    float m = -3.4e38f;
    for (int s = t; s < SS; s += 256) m = fmaxf(m, sh_w[s]);
#pragma unroll
    for (int o = 16; o; o >>= 1) m = fmaxf(m, __shfl_xor_sync(~0u, m, o));
    if (lane == 0) sh_red[w] = m;
    __syncthreads();
    m = sh_red[0];
#pragma unroll
    for (int i = 1; i < 8; i++) m = fmaxf(m, sh_red[i]);
    __syncthreads();

    float ssum = 0.f;
    for (int s = t; s < SS; s += 256) {
        float e = __expf(sh_w[s] - m);
        sh_w[s] = e;
        ssum += e;
    }
#pragma unroll
    for (int o = 16; o; o >>= 1) ssum += __shfl_xor_sync(~0u, ssum, o);
    if (lane == 0) sh_red[w] = ssum;
    __syncthreads();
    ssum = 0.f;
#pragma unroll
    for (int i = 0; i < 8; i++) ssum += sh_red[i];
    float inv = 1.f / ssum;
    __syncthreads();

    for (int s = t; s < SS; s += 256) {
        float wv = sh_w[s] * inv;
        sh_w[s] = wv;
        if (hh == 0) g_attw[b * SS + s] = wv;
    }
    __syncthreads();

    int h = hh * 256 + t;
    const float* encb = enc + (size_t)b * (SS * HH) + h;
    float a = 0.f;
#pragma unroll 4
    for (int s = 0; s < SS; s++) a = fmaf(sh_w[s], encb[s * HH], a);
    g_outcat[b * KOUT + 512 + h] = tf32r(a);   // pre-rounded for tf32 MMA
    g_gcat[b * KPAD + 300 + h] = a;            // exact
}

// ---------------- gate bias init ----------------------------------------------
__global__ void k_gbias(const float* __restrict__ bih, const float* __restrict__ bhh) {
    int idx = blockIdx.x * 256 + threadIdx.x;
    if (idx < BB * GR) {
        int r = idx & (GR - 1);
        g_gates[idx] = bih[r] + bhh[r];
    }
}

// ---------------- gates GEMM: tf32 mma + cp.async 2-stage ----------------------
#define GP 36
#define G_ASZ (64 * GP)
#define G_BSZ (128 * GP)
#define G_STG (G_ASZ + G_BSZ)
__global__ void __launch_bounds__(256) k_gates(const float* __restrict__ Wih,
                                               const float* __restrict__ Whh) {
    int t = threadIdx.x;
    int wid = t >> 5, lane = t & 31;
    int gid = lane >> 2, tig = lane & 3;
    int r0 = blockIdx.x * 128;
    int cbase = blockIdx.y * 6;
    int m0 = (wid & 1) * 32;
    int n0 = (wid >> 1) * 32;
    uint32_t smb = smem_u32(dynsmem);

    float acc[2][4][4];
#pragma unroll
    for (int mt = 0; mt < 2; mt++)
#pragma unroll
        for (int nt = 0; nt < 4; nt++)
#pragma unroll
            for (int p = 0; p < 4; p++) acc[mt][nt][p] = 0.f;

#define G_ISSUE(s, c) do {                                                         \
        uint32_t sa = smb + (s) * G_STG * 4;                                       \
        uint32_t sb = sa + G_ASZ * 4;                                              \
        int kbase = (c) * 32;                                                      \
        _Pragma("unroll")                                                          \
        for (int q = 0; q < 2; q++) {                                              \
            int i = q * 256 + t, row = i >> 3, c4 = i & 7;                         \
            cp_async16(sa + (row * GP + c4 * 4) * 4,                               \
                       g_gcat + (size_t)row * KPAD + kbase + c4 * 4, 16);          \
        }                                                                          \
        _Pragma("unroll")                                                          \
        for (int q = 0; q < 4; q++) {                                              \
            int i = q * 256 + t, row = i >> 3, c4 = i & 7;                         \
            int gr = r0 + row, k = kbase + c4 * 4;                                 \
            const float* src; int sz = 16;                                         \
            if (k < 812)       src = Wih + (size_t)gr * 812 + k;                   \
            else if (k < KG)   src = Whh + (size_t)gr * 512 + (k - 812);           \
            else             { src = Whh; sz = 0; }                                \
            cp_async16(sb + (row * GP + c4 * 4) * 4, src, sz);                     \
        }                                                                          \
        CP_COMMIT();                                                               \
    } while (0)

    G_ISSUE(0, cbase);
    for (int j = 0; j < 6; j++) {
        if (j + 1 < 6) G_ISSUE((j + 1) & 1, cbase + j + 1); else CP_COMMIT();
        CP_WAIT(1);
        __syncthreads();
        const float* sA = dynsmem + (j & 1) * G_STG;
        const float* sB = sA + G_ASZ;
#pragma unroll
        for (int ks = 0; ks < 4; ks++) {
            int kb = ks * 8;
            uint32_t a[2][4], b[4][2];
#pragma unroll
            for (int mt = 0; mt < 2; mt++) {
                int r = m0 + mt * 16 + gid;
                a[mt][0] = f2tf32(sA[r * GP + kb + tig]);
                a[mt][1] = f2tf32(sA[(r + 8) * GP + kb + tig]);
                a[mt][2] = f2tf32(sA[r * GP + kb + tig + 4]);
                a[mt][3] = f2tf32(sA[(r + 8) * GP + kb + tig + 4]);
            }
#pragma unroll
            for (int nt = 0; nt < 4; nt++) {
                int rn = n0 + nt * 8 + gid;
                b[nt][0] = f2tf32(sB[rn * GP + kb + tig]);
                b[nt][1] = f2tf32(sB[rn * GP + kb + tig + 4]);
            }
#pragma unroll
            for (int mt = 0; mt < 2; mt++)
#pragma unroll
                for (int nt = 0; nt < 4; nt++)
                    mma_tf32(acc[mt][nt], a[mt], b[nt]);
        }
        __syncthreads();
    }

#pragma unroll
    for (int mt = 0; mt < 2; mt++) {
        int r = m0 + mt * 16 + gid;
#pragma unroll
        for (int nt = 0; nt < 4; nt++) {
            int col = r0 + n0 + nt * 8 + 2 * tig;
            atomicAdd(&g_gates[r * GR + col],       acc[mt][nt][0]);
            atomicAdd(&g_gates[r * GR + col + 1],   acc[mt][nt][1]);
            atomicAdd(&g_gates[(r + 8) * GR + col],     acc[mt][nt][2]);
            atomicAdd(&g_gates[(r + 8) * GR + col + 1], acc[mt][nt][3]);
        }
    }
}

// ---------------- LSTM elementwise ---------------------------------------------
__global__ void k_lstm(const float* __restrict__ c0, float* __restrict__ out) {
    int idx = blockIdx.x * 256 + threadIdx.x;
    int b = idx >> 9, h = idx & (HH - 1);
    const float* g = g_gates + b * GR;
    float gi = g[h], gf = g[HH + h], gg = g[2 * HH + h], go = g[3 * HH + h];
    float c = fast_sigm(gf) * c0[idx] + fast_sigm(gi) * fast_tanh(gg);
    float hn = fast_sigm(go) * fast_tanh(c);
    out[OUT_H_OFF + idx] = hn;
    out[OUT_C_OFF + idx] = c;
    g_outcat[b * KOUT + h] = tf32r(hn);   // pre-rounded for tf32 MMA
}

// ---------------- p_gen ---------------------------------------------------------
__global__ void k_pgen(const float* __restrict__ genw, const float* __restrict__ genb) {
    int b = blockIdx.x * 8 + (threadIdx.x >> 5);
    int lane = threadIdx.x & 31;
    float p = 0.f;
    for (int k = lane; k < KG; k += 32) {
        float a;
        if (k < HH) a = g_outcat[b * KOUT + 512 + k];           // ctx (tf32-rounded)
        else if (k < 2 * HH) a = g_outcat[b * KOUT + (k - HH)]; // h_new (tf32-rounded)
        else a = g_gcat[b * KPAD + (k - 2 * HH)];               // xe exact
        p = fmaf(a, genw[k], p);
    }
#pragma unroll
    for (int o = 16; o; o >>= 1) p += __shfl_xor_sync(~0u, p, o);
    if (lane == 0) g_pgen[b] = fast_sigm(p + genb[0]);
}

// ---------------- output GEMM: tf32 mma, CTA 64x256, warp 32x64, 2-stage -------
#define OP 36
#define O_ASZ (64 * OP)
#define O_BSZ (256 * OP)
#define O_STG (O_ASZ + O_BSZ)
__global__ void __launch_bounds__(256) k_outgemm(const float* __restrict__ outw,
                                                 const float* __restrict__ outb,
                                                 float* __restrict__ out) {
    int t = threadIdx.x;
    int wid = t >> 5, lane = t & 31;
    int gid = lane >> 2, tig = lane & 3;
    int nb = blockIdx.x * 256;
    int m0 = (wid & 1) * 32;
    int n0 = (wid >> 1) * 64;
    uint32_t smb = smem_u32(dynsmem);

    float acc[2][8][4];
#pragma unroll
    for (int mt = 0; mt < 2; mt++)
#pragma unroll
        for (int nt = 0; nt < 8; nt++)
#pragma unroll
            for (int p = 0; p < 4; p++) acc[mt][nt][p] = 0.f;

#define O_ISSUE(s, kc) do {                                                        \
        uint32_t sa = smb + (s) * O_STG * 4;                                       \
        uint32_t sb = sa + O_ASZ * 4;                                              \
        int kbase = (kc) * 32;                                                     \
        _Pragma("unroll")                                                          \
        for (int q = 0; q < 2; q++) {                                              \
            int i = q * 256 + t, row = i >> 3, c4 = i & 7;                         \
            cp_async16(sa + (row * OP + c4 * 4) * 4,                               \
                       g_outcat + (size_t)row * KOUT + kbase + c4 * 4, 16);        \
        }                                                                          \
        _Pragma("unroll")                                                          \
        for (int q = 0; q < 8; q++) {                                              \
            int i = q * 256 + t, row = i >> 3, c4 = i & 7;                         \
            int vr = nb + row;                                                     \
            const float* src = outw;                                               \
            int sz = 0;                                                            \
            if (vr < VOCAB) { src = outw + (size_t)vr * KOUT + kbase + c4 * 4; sz = 16; } \
            cp_async16(sb + (row * OP + c4 * 4) * 4, src, sz);                     \
        }                                                                          \
        CP_COMMIT();                                                               \
    } while (0)

    O_ISSUE(0, 0);
    for (int kc = 0; kc < 32; kc++) {
        if (kc + 1 < 32) O_ISSUE((kc + 1) & 1, kc + 1); else CP_COMMIT();
        CP_WAIT(1);
        __syncthreads();
        const uint32_t* sA = reinterpret_cast<const uint32_t*>(dynsmem + (kc & 1) * O_STG);
        const float*    sB = dynsmem + (kc & 1) * O_STG + O_ASZ;
#pragma unroll
        for (int ks = 0; ks < 4; ks++) {
            int kb = ks * 8;
            uint32_t a[2][4], b[8][2];
#pragma unroll
            for (int mt = 0; mt < 2; mt++) {
                int r = m0 + mt * 16 + gid;
                a[mt][0] = sA[r * OP + kb + tig];            // pre-rounded tf32 bits
                a[mt][1] = sA[(r + 8) * OP + kb + tig];
                a[mt][2] = sA[r * OP + kb + tig + 4];
                a[mt][3] = sA[(r + 8) * OP + kb + tig + 4];
            }
#pragma unroll
            for (int nt = 0; nt < 8; nt++) {
                int rn = n0 + nt * 8 + gid;
                b[nt][0] = f2tf32(sB[rn * OP + kb + tig]);
                b[nt][1] = f2tf32(sB[rn * OP + kb + tig + 4]);
            }
#pragma unroll
            for (int mt = 0; mt < 2; mt++)
#pragma unroll
                for (int nt = 0; nt < 8; nt++)
                    mma_tf32(acc[mt][nt], a[mt], b[nt]);
        }
        __syncthreads();
    }

#pragma unroll
    for (int mt = 0; mt < 2; mt++) {
        int r = m0 + mt * 16 + gid;
        float pg0 = g_pgen[r], pg1 = g_pgen[r + 8];
#pragma unroll
        for (int nt = 0; nt < 8; nt++) {
            int v0 = nb + n0 + nt * 8 + 2 * tig;
            if (v0 < VOCAB) {
                float2 ob = *reinterpret_cast<const float2*>(outb + v0);
                float2 o0, o1;
                o0.x = pg0 * (acc[mt][nt][0] + ob.x);
                o0.y = pg0 * (acc[mt][nt][1] + ob.y);
                o1.x = pg1 * (acc[mt][nt][2] + ob.x);
                o1.y = pg1 * (acc[mt][nt][3] + ob.y);
                *reinterpret_cast<float2*>(out + (size_t)r * VOCAB + v0) = o0;
                *reinterpret_cast<float2*>(out + (size_t)(r + 8) * VOCAB + v0) = o1;
            }
        }
    }
}

// ---------------- pointer scatter ----------------------------------------------
__global__ void k_scatter(const int* __restrict__ text, float* __restrict__ out) {
    __shared__ int sv[SS];
    __shared__ float sw[SS];
    int b = blockIdx.x, t = threadIdx.x;
    for (int s = t; s < SS; s += 256) {
        sv[s] = text[b * SS + s];
        sw[s] = g_attw[b * SS + s];
    }
    __syncthreads();
    float pptr = 1.f - g_pgen[b];
    for (int s = t; s < SS; s += 256) {
        int v = sv[s];
        bool last = true;
        for (int s2 = s + 1; s2 < SS; s2++)
            if (sv[s2] == v) { last = false; break; }
        if (last) out[(size_t)b * VOCAB + v] += pptr * sw[s];
    }
}

// ---------------- launch --------------------------------------------------------
extern "C" void kernel_launch(void* const* d_in, const int* in_sizes, int n_in,
                              void* d_out, int out_size) {
    int sh = (n_in >= 17 && in_sizes[5] == 1) ? 1 : 0;
    const int*   x    = (const int*)  d_in[0];
    const float* enc  = (const float*)d_in[1];
    const float* h0   = (const float*)d_in[2];
    const float* c0   = (const float*)d_in[3];
    const int*   text = (const int*)  d_in[4];
    const float* emb  = (const float*)d_in[5 + sh];
    const float* Vw   = (const float*)d_in[6 + sh];
    const float* Vb   = (const float*)d_in[7 + sh];
    const float* genw = (const float*)d_in[8 + sh];
    const float* genb = (const float*)d_in[9 + sh];
    const float* outw = (const float*)d_in[10 + sh];
    const float* outb = (const float*)d_in[11 + sh];
    const float* Wih  = (const float*)d_in[12 + sh];
    const float* Whh  = (const float*)d_in[13 + sh];
    const float* bih  = (const float*)d_in[14 + sh];
    const float* bhh  = (const float*)d_in[15 + sh];
    float* out = (float*)d_out;

    cudaFuncSetAttribute(k_outgemm, cudaFuncAttributeMaxDynamicSharedMemorySize,
                         2 * O_STG * 4);
    cudaFuncSetAttribute(k_gates, cudaFuncAttributeMaxDynamicSharedMemorySize,
                         2 * G_STG * 4);

    k_embed<<<75, 256>>>(x, emb);
    dim3 gs(64, 2);
    k_score<<<gs, 256>>>(enc, h0, Vw, Vb);
    k_ctx<<<gs, 256>>>(enc);
    k_gbias<<<512, 256>>>(bih, bhh);
    dim3 gg(16, 8);
    k_gates<<<gg, 256, 2 * G_STG * 4>>>(Wih, Whh);
    k_lstm<<<128, 256>>>(c0, out);
    k_pgen<<<8, 256>>>(genw, genb);
    k_outgemm<<<196, 256, 2 * O_STG * 4>>>(outw, outb, out);
    k_scatter<<<64, 256>>>(text, out);
}

// round 7
// speedup vs baseline: 2.4098x; 1.1832x over previous
#include <cuda_runtime.h>
#include <cstdint>

#define BB 64
#define SS 400
#define HH 512
#define EE 300
#define VOCAB 50000
#define KOUT 1024
#define KG   1324
#define KPAD 1536
#define GR   2048

#define OUT_H_OFF (BB * VOCAB)
#define OUT_C_OFF (BB * VOCAB + BB * HH)

// ---------------- scratch ----------------------------------------------------
__device__ float g_attw[BB * SS];
__device__ float g_gcat[BB * KPAD];     // [b][k]: xe | ctx | hprev | 0-pad (exact fp32)
__device__ float g_outcat[BB * KOUT];   // [b][k]: h_new | ctx  (tf32-rounded bits)
__device__ float g_gates[BB * GR];
__device__ float g_pgen[BB];

__device__ __forceinline__ float fast_tanh(float x) {
    float e = __expf(x + x);
    return 1.f - __fdividef(2.f, e + 1.f);
}
__device__ __forceinline__ float fast_sigm(float x) {
    return __fdividef(1.f, 1.f + __expf(-x));
}
__device__ __forceinline__ uint32_t f2tf32(float x) {
    uint32_t r; asm("cvt.rna.tf32.f32 %0, %1;" : "=r"(r) : "f"(x)); return r;
}
__device__ __forceinline__ float tf32r(float x) {
    return __uint_as_float(f2tf32(x));
}
__device__ __forceinline__ void mma_tf32(float* d, const uint32_t* a, const uint32_t* b) {
    asm volatile("mma.sync.aligned.m16n8k8.row.col.f32.tf32.tf32.f32 "
                 "{%0,%1,%2,%3}, {%4,%5,%6,%7}, {%8,%9}, {%0,%1,%2,%3};"
                 : "+f"(d[0]), "+f"(d[1]), "+f"(d[2]), "+f"(d[3])
                 : "r"(a[0]), "r"(a[1]), "r"(a[2]), "r"(a[3]),
                   "r"(b[0]), "r"(b[1]));
}
__device__ __forceinline__ uint32_t smem_u32(const void* p) {
    uint32_t a;
    asm("{ .reg .u64 t; cvta.to.shared.u64 t, %1; cvt.u32.u64 %0, t; }" : "=r"(a) : "l"(p));
    return a;
}
__device__ __forceinline__ void cp_async16(uint32_t dst, const void* src, int src_bytes) {
    asm volatile("cp.async.cg.shared.global [%0], [%1], 16, %2;"
                 :: "r"(dst), "l"(src), "r"(src_bytes) : "memory");
}
#define CP_COMMIT() asm volatile("cp.async.commit_group;" ::: "memory")
#define CP_WAIT(n)  asm volatile("cp.async.wait_group %0;" :: "n"(n) : "memory")

extern __shared__ float dynsmem[];

// ---------------- fused attention: embed + scores + softmax + ctx + gbias ------
// grid 64 (one CTA per batch row), 512 threads
__global__ void __launch_bounds__(512) k_attn(const int* __restrict__ x,
                                              const float* __restrict__ emb,
                                              const float* __restrict__ enc,
                                              const float* __restrict__ h0,
                                              const float* __restrict__ Vw,
                                              const float* __restrict__ Vb,
                                              const float* __restrict__ bih,
                                              const float* __restrict__ bhh) {
    __shared__ float sh_h[HH];
    __shared__ float sh_vw[HH];
    __shared__ float sh_sc[SS];
    __shared__ float sh_red[16];

    int b = blockIdx.x;
    int t = threadIdx.x;
    int lane = t & 31, w = t >> 5;

    // stage h_prev + Vw in smem; h_prev also to g_gcat
    {
        float hv = h0[b * HH + t];
        sh_h[t] = hv;
        sh_vw[t] = Vw[t];
        g_gcat[b * KPAD + 812 + t] = hv;
    }
    // embedding gather: xe -> g_gcat[0..299]
    {
        int row = x[b];
        if (t < EE) g_gcat[b * KPAD + t] = emb[(size_t)row * EE + t];
        if (t >= 512 - (KPAD - KG)) {}   // pad region stays zero (.bss)
    }
    // gate bias init: g_gates[b][r] = bih[r] + bhh[r]
#pragma unroll
    for (int q = 0; q < 4; q++) {
        int r = q * 512 + t;
        g_gates[b * GR + r] = bih[r] + bhh[r];
    }
    __syncthreads();

    const float* encb = enc + (size_t)b * (SS * HH);
    float vb = Vb[0];

    // scores: one warp per s (16 warps)
    for (int s = w; s < SS; s += 16) {
        const float* row = encb + s * HH;
        float p = 0.f;
#pragma unroll
        for (int j = 0; j < 16; j++) {
            int h = j * 32 + lane;
            p += fast_tanh(row[h] + sh_h[h]) * sh_vw[h];
        }
#pragma unroll
        for (int o = 16; o; o >>= 1) p += __shfl_xor_sync(~0u, p, o);
        if (lane == 0) sh_sc[s] = p + vb;
    }
    __syncthreads();

    // softmax over S
    float m = -3.4e38f;
    for (int s = t; s < SS; s += 512) m = fmaxf(m, sh_sc[s]);
#pragma unroll
    for (int o = 16; o; o >>= 1) m = fmaxf(m, __shfl_xor_sync(~0u, m, o));
    if (lane == 0) sh_red[w] = m;
    __syncthreads();
    m = sh_red[0];
#pragma unroll
    for (int i = 1; i < 16; i++) m = fmaxf(m, sh_red[i]);
    __syncthreads();

    float ssum = 0.f;
    for (int s = t; s < SS; s += 512) {
        float e = __expf(sh_sc[s] - m);
        sh_sc[s] = e;
        ssum += e;
    }
#pragma unroll
    for (int o = 16; o; o >>= 1) ssum += __shfl_xor_sync(~0u, ssum, o);
    if (lane == 0) sh_red[w] = ssum;
    __syncthreads();
    ssum = 0.f;
#pragma unroll
    for (int i = 0; i < 16; i++) ssum += sh_red[i];
    float inv = 1.f / ssum;
    __syncthreads();

    for (int s = t; s < SS; s += 512) {
        float wv = sh_sc[s] * inv;
        sh_sc[s] = wv;
        g_attw[b * SS + s] = wv;
    }
    __syncthreads();

    // ctx[h], h = t
    const float* ep = encb + t;
    float a = 0.f;
#pragma unroll 4
    for (int s = 0; s < SS; s++) a = fmaf(sh_sc[s], ep[s * HH], a);
    g_outcat[b * KOUT + 512 + t] = tf32r(a);
    g_gcat[b * KPAD + 300 + t] = a;
}

// ---------------- gates GEMM: tf32 mma + cp.async 2-stage ----------------------
#define GP 36
#define G_ASZ (64 * GP)
#define G_BSZ (128 * GP)
#define G_STG (G_ASZ + G_BSZ)
__global__ void __launch_bounds__(256, 2) k_gates(const float* __restrict__ Wih,
                                                  const float* __restrict__ Whh) {
    int t = threadIdx.x;
    int wid = t >> 5, lane = t & 31;
    int gid = lane >> 2, tig = lane & 3;
    int r0 = blockIdx.x * 128;
    int cbase = blockIdx.y * 6;
    int m0 = (wid & 1) * 32;
    int n0 = (wid >> 1) * 32;
    uint32_t smb = smem_u32(dynsmem);

    float acc[2][4][4];
#pragma unroll
    for (int mt = 0; mt < 2; mt++)
#pragma unroll
        for (int nt = 0; nt < 4; nt++)
#pragma unroll
            for (int p = 0; p < 4; p++) acc[mt][nt][p] = 0.f;

#define G_ISSUE(s, c) do {                                                         \
        uint32_t sa = smb + (s) * G_STG * 4;                                       \
        uint32_t sb = sa + G_ASZ * 4;                                              \
        int kbase = (c) * 32;                                                      \
        _Pragma("unroll")                                                          \
        for (int q = 0; q < 2; q++) {                                              \
            int i = q * 256 + t, row = i >> 3, c4 = i & 7;                         \
            cp_async16(sa + (row * GP + c4 * 4) * 4,                               \
                       g_gcat + (size_t)row * KPAD + kbase + c4 * 4, 16);          \
        }                                                                          \
        _Pragma("unroll")                                                          \
        for (int q = 0; q < 4; q++) {                                              \
            int i = q * 256 + t, row = i >> 3, c4 = i & 7;                         \
            int gr = r0 + row, k = kbase + c4 * 4;                                 \
            const float* src; int sz = 16;                                         \
            if (k < 812)       src = Wih + (size_t)gr * 812 + k;                   \
            else if (k < KG)   src = Whh + (size_t)gr * 512 + (k - 812);           \
            else             { src = Whh; sz = 0; }                                \
            cp_async16(sb + (row * GP + c4 * 4) * 4, src, sz);                     \
        }                                                                          \
        CP_COMMIT();                                                               \
    } while (0)

    G_ISSUE(0, cbase);
    for (int j = 0; j < 6; j++) {
        if (j + 1 < 6) G_ISSUE((j + 1) & 1, cbase + j + 1); else CP_COMMIT();
        CP_WAIT(1);
        __syncthreads();
        const float* sA = dynsmem + (j & 1) * G_STG;
        const float* sB = sA + G_ASZ;
#pragma unroll
        for (int ks = 0; ks < 4; ks++) {
            int kb = ks * 8;
            uint32_t a[2][4], b[4][2];
#pragma unroll
            for (int mt = 0; mt < 2; mt++) {
                int r = m0 + mt * 16 + gid;
                a[mt][0] = f2tf32(sA[r * GP + kb + tig]);
                a[mt][1] = f2tf32(sA[(r + 8) * GP + kb + tig]);
                a[mt][2] = f2tf32(sA[r * GP + kb + tig + 4]);
                a[mt][3] = f2tf32(sA[(r + 8) * GP + kb + tig + 4]);
            }
#pragma unroll
            for (int nt = 0; nt < 4; nt++) {
                int rn = n0 + nt * 8 + gid;
                b[nt][0] = f2tf32(sB[rn * GP + kb + tig]);
                b[nt][1] = f2tf32(sB[rn * GP + kb + tig + 4]);
            }
#pragma unroll
            for (int mt = 0; mt < 2; mt++)
#pragma unroll
                for (int nt = 0; nt < 4; nt++)
                    mma_tf32(acc[mt][nt], a[mt], b[nt]);
        }
        __syncthreads();
    }

#pragma unroll
    for (int mt = 0; mt < 2; mt++) {
        int r = m0 + mt * 16 + gid;
#pragma unroll
        for (int nt = 0; nt < 4; nt++) {
            int col = r0 + n0 + nt * 8 + 2 * tig;
            atomicAdd(&g_gates[r * GR + col],       acc[mt][nt][0]);
            atomicAdd(&g_gates[r * GR + col + 1],   acc[mt][nt][1]);
            atomicAdd(&g_gates[(r + 8) * GR + col],     acc[mt][nt][2]);
            atomicAdd(&g_gates[(r + 8) * GR + col + 1], acc[mt][nt][3]);
        }
    }
}

// ---------------- LSTM elementwise + p_gen (fused), grid 64 x 512 --------------
__global__ void __launch_bounds__(512) k_lstmpgen(const float* __restrict__ c0,
                                                  const float* __restrict__ genw,
                                                  const float* __restrict__ genb,
                                                  float* __restrict__ out) {
    __shared__ float sh_red[16];
    int b = blockIdx.x, t = threadIdx.x;
    int lane = t & 31, w = t >> 5;

    const float* g = g_gates + b * GR;
    float gi = g[t], gf = g[HH + t], gg = g[2 * HH + t], go = g[3 * HH + t];
    float c = fast_sigm(gf) * c0[b * HH + t] + fast_sigm(gi) * fast_tanh(gg);
    float hn = fast_sigm(go) * fast_tanh(c);
    out[OUT_H_OFF + b * HH + t] = hn;
    out[OUT_C_OFF + b * HH + t] = c;
    g_outcat[b * KOUT + t] = tf32r(hn);

    // p_gen partial: k = t (ctx), 512+t (h_new), 1024+t (xe, t<300)
    float ctxv = g_gcat[b * KPAD + 300 + t];   // exact ctx
    float p = genw[t] * ctxv + genw[512 + t] * hn;
    if (t < EE) p = fmaf(genw[1024 + t], g_gcat[b * KPAD + t], p);
#pragma unroll
    for (int o = 16; o; o >>= 1) p += __shfl_xor_sync(~0u, p, o);
    if (lane == 0) sh_red[w] = p;
    __syncthreads();
    if (t == 0) {
        float s = 0.f;
#pragma unroll
        for (int i = 0; i < 16; i++) s += sh_red[i];
        g_pgen[b] = fast_sigm(s + genb[0]);
    }
}

// ---------------- output GEMM: tf32 mma, CTA 64x256, warp 32x64, 2-stage -------
#define OP 36
#define O_ASZ (64 * OP)
#define O_BSZ (256 * OP)
#define O_STG (O_ASZ + O_BSZ)
__global__ void __launch_bounds__(256, 2) k_outgemm(const float* __restrict__ outw,
                                                    const float* __restrict__ outb,
                                                    float* __restrict__ out) {
    int t = threadIdx.x;
    int wid = t >> 5, lane = t & 31;
    int gid = lane >> 2, tig = lane & 3;
    int nb = blockIdx.x * 256;
    int m0 = (wid & 1) * 32;
    int n0 = (wid >> 1) * 64;
    uint32_t smb = smem_u32(dynsmem);

    float acc[2][8][4];
#pragma unroll
    for (int mt = 0; mt < 2; mt++)
#pragma unroll
        for (int nt = 0; nt < 8; nt++)
#pragma unroll
            for (int p = 0; p < 4; p++) acc[mt][nt][p] = 0.f;

#define O_ISSUE(s, kc) do {                                                        \
        uint32_t sa = smb + (s) * O_STG * 4;                                       \
        uint32_t sb = sa + O_ASZ * 4;                                              \
        int kbase = (kc) * 32;                                                     \
        _Pragma("unroll")                                                          \
        for (int q = 0; q < 2; q++) {                                              \
            int i = q * 256 + t, row = i >> 3, c4 = i & 7;                         \
            cp_async16(sa + (row * OP + c4 * 4) * 4,                               \
                       g_outcat + (size_t)row * KOUT + kbase + c4 * 4, 16);        \
        }                                                                          \
        _Pragma("unroll")                                                          \
        for (int q = 0; q < 8; q++) {                                              \
            int i = q * 256 + t, row = i >> 3, c4 = i & 7;                         \
            int vr = nb + row;                                                     \
            const float* src = outw;                                               \
            int sz = 0;                                                            \
            if (vr < VOCAB) { src = outw + (size_t)vr * KOUT + kbase + c4 * 4; sz = 16; } \
            cp_async16(sb + (row * OP + c4 * 4) * 4, src, sz);                     \
        }                                                                          \
        CP_COMMIT();                                                               \
    } while (0)

    O_ISSUE(0, 0);
    for (int kc = 0; kc < 32; kc++) {
        if (kc + 1 < 32) O_ISSUE((kc + 1) & 1, kc + 1); else CP_COMMIT();
        CP_WAIT(1);
        __syncthreads();
        const uint32_t* sA = reinterpret_cast<const uint32_t*>(dynsmem + (kc & 1) * O_STG);
        const float*    sB = dynsmem + (kc & 1) * O_STG + O_ASZ;
#pragma unroll
        for (int ks = 0; ks < 4; ks++) {
            int kb = ks * 8;
            uint32_t a[2][4], b[8][2];
#pragma unroll
            for (int mt = 0; mt < 2; mt++) {
                int r = m0 + mt * 16 + gid;
                a[mt][0] = sA[r * OP + kb + tig];
                a[mt][1] = sA[(r + 8) * OP + kb + tig];
                a[mt][2] = sA[r * OP + kb + tig + 4];
                a[mt][3] = sA[(r + 8) * OP + kb + tig + 4];
            }
#pragma unroll
            for (int nt = 0; nt < 8; nt++) {
                int rn = n0 + nt * 8 + gid;
                b[nt][0] = f2tf32(sB[rn * OP + kb + tig]);
                b[nt][1] = f2tf32(sB[rn * OP + kb + tig + 4]);
            }
#pragma unroll
            for (int mt = 0; mt < 2; mt++)
#pragma unroll
                for (int nt = 0; nt < 8; nt++)
                    mma_tf32(acc[mt][nt], a[mt], b[nt]);
        }
        __syncthreads();
    }

#pragma unroll
    for (int mt = 0; mt < 2; mt++) {
        int r = m0 + mt * 16 + gid;
        float pg0 = g_pgen[r], pg1 = g_pgen[r + 8];
#pragma unroll
        for (int nt = 0; nt < 8; nt++) {
            int v0 = nb + n0 + nt * 8 + 2 * tig;
            if (v0 < VOCAB) {
                float2 ob = *reinterpret_cast<const float2*>(outb + v0);
                float2 o0, o1;
                o0.x = pg0 * (acc[mt][nt][0] + ob.x);
                o0.y = pg0 * (acc[mt][nt][1] + ob.y);
                o1.x = pg1 * (acc[mt][nt][2] + ob.x);
                o1.y = pg1 * (acc[mt][nt][3] + ob.y);
                *reinterpret_cast<float2*>(out + (size_t)r * VOCAB + v0) = o0;
                *reinterpret_cast<float2*>(out + (size_t)(r + 8) * VOCAB + v0) = o1;
            }
        }
    }
}

// ---------------- pointer scatter ----------------------------------------------
__global__ void k_scatter(const int* __restrict__ text, float* __restrict__ out) {
    __shared__ int sv[SS];
    __shared__ float sw[SS];
    int b = blockIdx.x, t = threadIdx.x;
    for (int s = t; s < SS; s += 256) {
        sv[s] = text[b * SS + s];
        sw[s] = g_attw[b * SS + s];
    }
    __syncthreads();
    float pptr = 1.f - g_pgen[b];
    for (int s = t; s < SS; s += 256) {
        int v = sv[s];
        bool last = true;
        for (int s2 = s + 1; s2 < SS; s2++)
            if (sv[s2] == v) { last = false; break; }
        if (last) out[(size_t)b * VOCAB + v] += pptr * sw[s];
    }
}

// ---------------- launch --------------------------------------------------------
extern "C" void kernel_launch(void* const* d_in, const int* in_sizes, int n_in,
                              void* d_out, int out_size) {
    int sh = (n_in >= 17 && in_sizes[5] == 1) ? 1 : 0;
    const int*   x    = (const int*)  d_in[0];
    const float* enc  = (const float*)d_in[1];
    const float* h0   = (const float*)d_in[2];
    const float* c0   = (const float*)d_in[3];
    const int*   text = (const int*)  d_in[4];
    const float* emb  = (const float*)d_in[5 + sh];
    const float* Vw   = (const float*)d_in[6 + sh];
    const float* Vb   = (const float*)d_in[7 + sh];
    const float* genw = (const float*)d_in[8 + sh];
    const float* genb = (const float*)d_in[9 + sh];
    const float* outw = (const float*)d_in[10 + sh];
    const float* outb = (const float*)d_in[11 + sh];
    const float* Wih  = (const float*)d_in[12 + sh];
    const float* Whh  = (const float*)d_in[13 + sh];
    const float* bih  = (const float*)d_in[14 + sh];
    const float* bhh  = (const float*)d_in[15 + sh];
    float* out = (float*)d_out;

    cudaFuncSetAttribute(k_outgemm, cudaFuncAttributeMaxDynamicSharedMemorySize,
                         2 * O_STG * 4);
    cudaFuncSetAttribute(k_gates, cudaFuncAttributeMaxDynamicSharedMemorySize,
                         2 * G_STG * 4);

    k_attn<<<64, 512>>>(x, emb, enc, h0, Vw, Vb, bih, bhh);
    dim3 gg(16, 8);
    k_gates<<<gg, 256, 2 * G_STG * 4>>>(Wih, Whh);
    k_lstmpgen<<<64, 512>>>(c0, genw, genb, out);
    k_outgemm<<<196, 256, 2 * O_STG * 4>>>(outw, outb, out);
    k_scatter<<<64, 256>>>(text, out);
}

// round 8
// speedup vs baseline: 2.4579x; 1.0200x over previous
#include <cuda_runtime.h>
#include <cstdint>

#define BB 64
#define SS 400
#define HH 512
#define EE 300
#define VOCAB 50000
#define KOUT 1024
#define KG   1324
#define KPAD 1536
#define GR   2048

#define OUT_H_OFF (BB * VOCAB)
#define OUT_C_OFF (BB * VOCAB + BB * HH)

// ---------------- scratch ----------------------------------------------------
__device__ float g_attw[BB * SS];
__device__ float g_score[BB * SS];
__device__ float g_gcat[BB * KPAD];     // [b][k]: xe | ctx | hprev | 0-pad (exact fp32)
__device__ float g_outcat[BB * KOUT];   // [b][k]: h_new | ctx  (tf32-rounded bits)
__device__ float g_gates[BB * GR];
__device__ float g_pgen[BB];

__device__ __forceinline__ float fast_tanh(float x) {
    float e = __expf(x + x);
    return 1.f - __fdividef(2.f, e + 1.f);
}
__device__ __forceinline__ float fast_sigm(float x) {
    return __fdividef(1.f, 1.f + __expf(-x));
}
__device__ __forceinline__ uint32_t f2tf32(float x) {
    uint32_t r; asm("cvt.rna.tf32.f32 %0, %1;" : "=r"(r) : "f"(x)); return r;
}
__device__ __forceinline__ float tf32r(float x) {
    return __uint_as_float(f2tf32(x));
}
__device__ __forceinline__ void mma_tf32(float* d, const uint32_t* a, const uint32_t* b) {
    asm volatile("mma.sync.aligned.m16n8k8.row.col.f32.tf32.tf32.f32 "
                 "{%0,%1,%2,%3}, {%4,%5,%6,%7}, {%8,%9}, {%0,%1,%2,%3};"
                 : "+f"(d[0]), "+f"(d[1]), "+f"(d[2]), "+f"(d[3])
                 : "r"(a[0]), "r"(a[1]), "r"(a[2]), "r"(a[3]),
                   "r"(b[0]), "r"(b[1]));
}
__device__ __forceinline__ uint32_t smem_u32(const void* p) {
    uint32_t a;
    asm("{ .reg .u64 t; cvta.to.shared.u64 t, %1; cvt.u32.u64 %0, t; }" : "=r"(a) : "l"(p));
    return a;
}
__device__ __forceinline__ void cp_async16(uint32_t dst, const void* src, int src_bytes) {
    asm volatile("cp.async.cg.shared.global [%0], [%1], 16, %2;"
                 :: "r"(dst), "l"(src), "r"(src_bytes) : "memory");
}
#define CP_COMMIT() asm volatile("cp.async.commit_group;" ::: "memory")
#define CP_WAIT(n)  asm volatile("cp.async.wait_group %0;" :: "n"(n) : "memory")

extern __shared__ float dynsmem[];

// ---------------- scores (grid 64 x 4) + one-time staging ----------------------
__global__ void __launch_bounds__(256) k_score(const int* __restrict__ x,
                                               const float* __restrict__ emb,
                                               const float* __restrict__ enc,
                                               const float* __restrict__ h0,
                                               const float* __restrict__ Vw,
                                               const float* __restrict__ Vb,
                                               const float* __restrict__ bih,
                                               const float* __restrict__ bhh) {
    __shared__ float sh_h[HH];
    __shared__ float sh_vw[HH];
    int b = blockIdx.x, q4 = blockIdx.y;
    int t = threadIdx.x;
    int lane = t & 31, w = t >> 5;

    for (int i = t; i < HH; i += 256) {
        float hv = h0[b * HH + i];
        sh_h[i] = hv;
        sh_vw[i] = Vw[i];
        if (q4 == 0) g_gcat[b * KPAD + 812 + i] = hv;
    }
    if (q4 == 0) {
        int row = x[b];
        for (int i = t; i < EE; i += 256)
            g_gcat[b * KPAD + i] = emb[(size_t)row * EE + i];
        for (int i = t; i < GR; i += 256)
            g_gates[b * GR + i] = bih[i] + bhh[i];
    }
    __syncthreads();

    const float* encb = enc + (size_t)b * (SS * HH);
    float vb = Vb[0];
    int s0 = q4 * 100;
    for (int s = s0 + w; s < s0 + 100; s += 8) {
        const float* row = encb + s * HH;
        float p = 0.f;
#pragma unroll
        for (int j = 0; j < 16; j++) {
            int h = j * 32 + lane;
            p += fast_tanh(row[h] + sh_h[h]) * sh_vw[h];
        }
#pragma unroll
        for (int o = 16; o; o >>= 1) p += __shfl_xor_sync(~0u, p, o);
        if (lane == 0) g_score[b * SS + s] = p + vb;
    }
}

// ---------------- softmax + ctx (grid 64 x 2, h-halves) ------------------------
__global__ void __launch_bounds__(256) k_ctx(const float* __restrict__ enc) {
    __shared__ float sh_w[SS];
    __shared__ float sh_red[8];
    int b = blockIdx.x, hh = blockIdx.y;
    int t = threadIdx.x;
    int lane = t & 31, w = t >> 5;

    for (int s = t; s < SS; s += 256) sh_w[s] = g_score[b * SS + s];
    __syncthreads();

    float m = -3.4e38f;
    for (int s = t; s < SS; s += 256) m = fmaxf(m, sh_w[s]);
#pragma unroll
    for (int o = 16; o; o >>= 1) m = fmaxf(m, __shfl_xor_sync(~0u, m, o));
    if (lane == 0) sh_red[w] = m;
    __syncthreads();
    m = sh_red[0];
#pragma unroll
    for (int i = 1; i < 8; i++) m = fmaxf(m, sh_red[i]);
    __syncthreads();

    float ssum = 0.f;
    for (int s = t; s < SS; s += 256) {
        float e = __expf(sh_w[s] - m);
        sh_w[s] = e;
        ssum += e;
    }
#pragma unroll
    for (int o = 16; o; o >>= 1) ssum += __shfl_xor_sync(~0u, ssum, o);
    if (lane == 0) sh_red[w] = ssum;
    __syncthreads();
    ssum = 0.f;
#pragma unroll
    for (int i = 0; i < 8; i++) ssum += sh_red[i];
    float inv = 1.f / ssum;
    __syncthreads();

    for (int s = t; s < SS; s += 256) {
        float wv = sh_w[s] * inv;
        sh_w[s] = wv;
        if (hh == 0) g_attw[b * SS + s] = wv;
    }
    __syncthreads();

    int h = hh * 256 + t;
    const float* encb = enc + (size_t)b * (SS * HH) + h;
    float a = 0.f;
#pragma unroll 4
    for (int s = 0; s < SS; s++) a = fmaf(sh_w[s], encb[s * HH], a);
    g_outcat[b * KOUT + 512 + h] = tf32r(a);
    g_gcat[b * KPAD + 300 + h] = a;
}

// ---------------- gates GEMM: tf32 mma + cp.async 2-stage ----------------------
#define GP 36
#define G_ASZ (64 * GP)
#define G_BSZ (128 * GP)
#define G_STG (G_ASZ + G_BSZ)
__global__ void __launch_bounds__(256, 2) k_gates(const float* __restrict__ Wih,
                                                  const float* __restrict__ Whh) {
    int t = threadIdx.x;
    int wid = t >> 5, lane = t & 31;
    int gid = lane >> 2, tig = lane & 3;
    int r0 = blockIdx.x * 128;
    int cbase = blockIdx.y * 6;
    int m0 = (wid & 1) * 32;
    int n0 = (wid >> 1) * 32;
    uint32_t smb = smem_u32(dynsmem);

    float acc[2][4][4];
#pragma unroll
    for (int mt = 0; mt < 2; mt++)
#pragma unroll
        for (int nt = 0; nt < 4; nt++)
#pragma unroll
            for (int p = 0; p < 4; p++) acc[mt][nt][p] = 0.f;

#define G_ISSUE(s, c) do {                                                         \
        uint32_t sa = smb + (s) * G_STG * 4;                                       \
        uint32_t sb = sa + G_ASZ * 4;                                              \
        int kbase = (c) * 32;                                                      \
        _Pragma("unroll")                                                          \
        for (int q = 0; q < 2; q++) {                                              \
            int i = q * 256 + t, row = i >> 3, c4 = i & 7;                         \
            cp_async16(sa + (row * GP + c4 * 4) * 4,                               \
                       g_gcat + (size_t)row * KPAD + kbase + c4 * 4, 16);          \
        }                                                                          \
        _Pragma("unroll")                                                          \
        for (int q = 0; q < 4; q++) {                                              \
            int i = q * 256 + t, row = i >> 3, c4 = i & 7;                         \
            int gr = r0 + row, k = kbase + c4 * 4;                                 \
            const float* src; int sz = 16;                                         \
            if (k < 812)       src = Wih + (size_t)gr * 812 + k;                   \
            else if (k < KG)   src = Whh + (size_t)gr * 512 + (k - 812);           \
            else             { src = Whh; sz = 0; }                                \
            cp_async16(sb + (row * GP + c4 * 4) * 4, src, sz);                     \
        }                                                                          \
        CP_COMMIT();                                                               \
    } while (0)

    G_ISSUE(0, cbase);
    for (int j = 0; j < 6; j++) {
        if (j + 1 < 6) G_ISSUE((j + 1) & 1, cbase + j + 1); else CP_COMMIT();
        CP_WAIT(1);
        __syncthreads();
        const float* sA = dynsmem + (j & 1) * G_STG;
        const float* sB = sA + G_ASZ;
#pragma unroll
        for (int ks = 0; ks < 4; ks++) {
            int kb = ks * 8;
            uint32_t a[2][4], b[4][2];
#pragma unroll
            for (int mt = 0; mt < 2; mt++) {
                int r = m0 + mt * 16 + gid;
                a[mt][0] = f2tf32(sA[r * GP + kb + tig]);
                a[mt][1] = f2tf32(sA[(r + 8) * GP + kb + tig]);
                a[mt][2] = f2tf32(sA[r * GP + kb + tig + 4]);
                a[mt][3] = f2tf32(sA[(r + 8) * GP + kb + tig + 4]);
            }
#pragma unroll
            for (int nt = 0; nt < 4; nt++) {
                int rn = n0 + nt * 8 + gid;
                b[nt][0] = f2tf32(sB[rn * GP + kb + tig]);
                b[nt][1] = f2tf32(sB[rn * GP + kb + tig + 4]);
            }
#pragma unroll
            for (int mt = 0; mt < 2; mt++)
#pragma unroll
                for (int nt = 0; nt < 4; nt++)
                    mma_tf32(acc[mt][nt], a[mt], b[nt]);
        }
        __syncthreads();
    }

#pragma unroll
    for (int mt = 0; mt < 2; mt++) {
        int r = m0 + mt * 16 + gid;
#pragma unroll
        for (int nt = 0; nt < 4; nt++) {
            int col = r0 + n0 + nt * 8 + 2 * tig;
            atomicAdd(&g_gates[r * GR + col],       acc[mt][nt][0]);
            atomicAdd(&g_gates[r * GR + col + 1],   acc[mt][nt][1]);
            atomicAdd(&g_gates[(r + 8) * GR + col],     acc[mt][nt][2]);
            atomicAdd(&g_gates[(r + 8) * GR + col + 1], acc[mt][nt][3]);
        }
    }
}

// ---------------- LSTM elementwise + p_gen (fused), grid 64 x 512 --------------
__global__ void __launch_bounds__(512) k_lstmpgen(const float* __restrict__ c0,
                                                  const float* __restrict__ genw,
                                                  const float* __restrict__ genb,
                                                  float* __restrict__ out) {
    __shared__ float sh_red[16];
    int b = blockIdx.x, t = threadIdx.x;
    int lane = t & 31, w = t >> 5;

    const float* g = g_gates + b * GR;
    float gi = g[t], gf = g[HH + t], gg = g[2 * HH + t], go = g[3 * HH + t];
    float c = fast_sigm(gf) * c0[b * HH + t] + fast_sigm(gi) * fast_tanh(gg);
    float hn = fast_sigm(go) * fast_tanh(c);
    out[OUT_H_OFF + b * HH + t] = hn;
    out[OUT_C_OFF + b * HH + t] = c;
    g_outcat[b * KOUT + t] = tf32r(hn);

    float ctxv = g_gcat[b * KPAD + 300 + t];
    float p = genw[t] * ctxv + genw[512 + t] * hn;
    if (t < EE) p = fmaf(genw[1024 + t], g_gcat[b * KPAD + t], p);
#pragma unroll
    for (int o = 16; o; o >>= 1) p += __shfl_xor_sync(~0u, p, o);
    if (lane == 0) sh_red[w] = p;
    __syncthreads();
    if (t == 0) {
        float s = 0.f;
#pragma unroll
        for (int i = 0; i < 16; i++) s += sh_red[i];
        g_pgen[b] = fast_sigm(s + genb[0]);
    }
}

// ---------------- output GEMM: tf32 mma, CTA 64x128, warp 16x64, 2-stage -------
// 8 warps in 4(m) x 2(n); 3 CTAs/SM for latency hiding.
#define OP 36
#define O_ASZ (64 * OP)
#define O_BSZ (128 * OP)
#define O_STG (O_ASZ + O_BSZ)
__global__ void __launch_bounds__(256, 3) k_outgemm(const float* __restrict__ outw,
                                                    const float* __restrict__ outb,
                                                    float* __restrict__ out) {
    int t = threadIdx.x;
    int wid = t >> 5, lane = t & 31;
    int gid = lane >> 2, tig = lane & 3;
    int nb = blockIdx.x * 128;
    int m0 = (wid & 3) * 16;
    int n0 = (wid >> 2) * 64;
    uint32_t smb = smem_u32(dynsmem);

    float acc[8][4];
#pragma unroll
    for (int nt = 0; nt < 8; nt++)
#pragma unroll
        for (int p = 0; p < 4; p++) acc[nt][p] = 0.f;

#define O_ISSUE(s, kc) do {                                                        \
        uint32_t sa = smb + (s) * O_STG * 4;                                       \
        uint32_t sb = sa + O_ASZ * 4;                                               \
        int kbase = (kc) * 32;                                                     \
        _Pragma("unroll")                                                          \
        for (int q = 0; q < 2; q++) {                                              \
            int i = q * 256 + t, row = i >> 3, c4 = i & 7;                         \
            cp_async16(sa + (row * OP + c4 * 4) * 4,                               \
                       g_outcat + (size_t)row * KOUT + kbase + c4 * 4, 16);        \
        }                                                                          \
        _Pragma("unroll")                                                          \
        for (int q = 0; q < 4; q++) {                                              \
            int i = q * 256 + t, row = i >> 3, c4 = i & 7;                         \
            int vr = nb + row;                                                     \
            const float* src = outw;                                               \
            int sz = 0;                                                            \
            if (vr < VOCAB) { src = outw + (size_t)vr * KOUT + kbase + c4 * 4; sz = 16; } \
            cp_async16(sb + (row * OP + c4 * 4) * 4, src, sz);                     \
        }                                                                          \
        CP_COMMIT();                                                               \
    } while (0)

    O_ISSUE(0, 0);
    for (int kc = 0; kc < 32; kc++) {
        if (kc + 1 < 32) O_ISSUE((kc + 1) & 1, kc + 1); else CP_COMMIT();
        CP_WAIT(1);
        __syncthreads();
        const uint32_t* sA = reinterpret_cast<const uint32_t*>(dynsmem + (kc & 1) * O_STG);
        const float*    sB = dynsmem + (kc & 1) * O_STG + O_ASZ;
#pragma unroll
        for (int ks = 0; ks < 4; ks++) {
            int kb = ks * 8;
            uint32_t a[4];
            int r = m0 + gid;
            a[0] = sA[r * OP + kb + tig];
            a[1] = sA[(r + 8) * OP + kb + tig];
            a[2] = sA[r * OP + kb + tig + 4];
            a[3] = sA[(r + 8) * OP + kb + tig + 4];
#pragma unroll
            for (int nt = 0; nt < 8; nt++) {
                int rn = n0 + nt * 8 + gid;
                uint32_t b[2];
                b[0] = f2tf32(sB[rn * OP + kb + tig]);
                b[1] = f2tf32(sB[rn * OP + kb + tig + 4]);
                mma_tf32(acc[nt], a, b);
            }
        }
        __syncthreads();
    }

    {
        int r = m0 + gid;
        float pg0 = g_pgen[r], pg1 = g_pgen[r + 8];
#pragma unroll
        for (int nt = 0; nt < 8; nt++) {
            int v0 = nb + n0 + nt * 8 + 2 * tig;
            if (v0 < VOCAB) {
                float2 ob = *reinterpret_cast<const float2*>(outb + v0);
                float2 o0, o1;
                o0.x = pg0 * (acc[nt][0] + ob.x);
                o0.y = pg0 * (acc[nt][1] + ob.y);
                o1.x = pg1 * (acc[nt][2] + ob.x);
                o1.y = pg1 * (acc[nt][3] + ob.y);
                *reinterpret_cast<float2*>(out + (size_t)r * VOCAB + v0) = o0;
                *reinterpret_cast<float2*>(out + (size_t)(r + 8) * VOCAB + v0) = o1;
            }
        }
    }
}

// ---------------- pointer scatter ----------------------------------------------
__global__ void k_scatter(const int* __restrict__ text, float* __restrict__ out) {
    __shared__ int sv[SS];
    __shared__ float sw[SS];
    int b = blockIdx.x, t = threadIdx.x;
    for (int s = t; s < SS; s += 256) {
        sv[s] = text[b * SS + s];
        sw[s] = g_attw[b * SS + s];
    }
    __syncthreads();
    float pptr = 1.f - g_pgen[b];
    for (int s = t; s < SS; s += 256) {
        int v = sv[s];
        bool last = true;
        for (int s2 = s + 1; s2 < SS; s2++)
            if (sv[s2] == v) { last = false; break; }
        if (last) out[(size_t)b * VOCAB + v] += pptr * sw[s];
    }
}

// ---------------- launch --------------------------------------------------------
extern "C" void kernel_launch(void* const* d_in, const int* in_sizes, int n_in,
                              void* d_out, int out_size) {
    int sh = (n_in >= 17 && in_sizes[5] == 1) ? 1 : 0;
    const int*   x    = (const int*)  d_in[0];
    const float* enc  = (const float*)d_in[1];
    const float* h0   = (const float*)d_in[2];
    const float* c0   = (const float*)d_in[3];
    const int*   text = (const int*)  d_in[4];
    const float* emb  = (const float*)d_in[5 + sh];
    const float* Vw   = (const float*)d_in[6 + sh];
    const float* Vb   = (const float*)d_in[7 + sh];
    const float* genw = (const float*)d_in[8 + sh];
    const float* genb = (const float*)d_in[9 + sh];
    const float* outw = (const float*)d_in[10 + sh];
    const float* outb = (const float*)d_in[11 + sh];
    const float* Wih  = (const float*)d_in[12 + sh];
    const float* Whh  = (const float*)d_in[13 + sh];
    const float* bih  = (const float*)d_in[14 + sh];
    const float* bhh  = (const float*)d_in[15 + sh];
    float* out = (float*)d_out;

    cudaFuncSetAttribute(k_outgemm, cudaFuncAttributeMaxDynamicSharedMemorySize,
                         2 * O_STG * 4);
    cudaFuncSetAttribute(k_gates, cudaFuncAttributeMaxDynamicSharedMemorySize,
                         2 * G_STG * 4);

    dim3 gsc(64, 4);
    k_score<<<gsc, 256>>>(x, emb, enc, h0, Vw, Vb, bih, bhh);
    dim3 gcx(64, 2);
    k_ctx<<<gcx, 256>>>(enc);
    dim3 gg(16, 8);
    k_gates<<<gg, 256, 2 * G_STG * 4>>>(Wih, Whh);
    k_lstmpgen<<<64, 512>>>(c0, genw, genb, out);
    k_outgemm<<<391, 256, 2 * O_STG * 4>>>(outw, outb, out);
    k_scatter<<<64, 256>>>(text, out);
}